// round 15
// baseline (speedup 1.0000x reference)
#include <cuda_runtime.h>
#include <cuda_fp16.h>
#include <stdint.h>
#include <math.h>

#define FD   64
#define SFD  384
#define NITD 3
#define NBD  256
#define MAXN 50000
#define MAXE 400000
#define MAXLE 1600000

static inline int cdiv(int a, int b){ return (a + b - 1) / b; }

// ---------------- scratch ----------------
__device__ float  g_xuv[(size_t)MAXN*128];
__device__ float  g_ea[(size_t)MAXE*FD];           // fp32 ea (reverted)
__device__ __half g_outh[NITD][(size_t)MAXE*FD];   // fp16 out
__device__ int   g_counts[MAXE];
__device__ int   g_offsets[MAXE+1];
__device__ int   g_cursor[MAXE];
__device__ int   g_ncounts[MAXN];
__device__ int   g_noffsets[MAXN+1];
__device__ int   g_ncursor[MAXN];
__device__ int   g_nidx[MAXE];
__device__ int   g_bsum[1024];
__device__ int   g_idx[MAXLE];
__device__ float g_xw[NITD][MAXE];
__device__ float g_xc[MAXE];
__device__ int   g_segstart[NBD+1];
__device__ float g_pm[NBD];
__device__ float g_pd[NBD];
__device__ float g_gout[NBD*FD];
__device__ float g_gt[NITD*NBD*FD];
__device__ float g_scatt[NBD*NITD];
__device__ float g_xn[(size_t)MAXN*FD];
__device__ __half g_bufA[(size_t)MAXN*SFD];        // fp16 intermediates
__device__ __half g_bufB[(size_t)MAXN*SFD];
__device__ __half g_bufC[(size_t)MAXN*SFD];
__device__ float g_ssum5[5*SFD];
__device__ float g_ssq5[5*SFD];
__device__ uint32_t g_W1t[FD*SFD];
__device__ uint32_t g_Wmt[3*SFD*SFD];
__device__ uint32_t g_W5t[SFD*128];

// ---------------- tf32 helpers ----------------
__device__ __forceinline__ uint32_t f2tf32(float v){
    uint32_t o; asm("cvt.rna.tf32.f32 %0, %1;" : "=r"(o) : "f"(v)); return o;
}
__device__ __forceinline__ void mma_tf32(float (&c)[4],
    uint32_t a0, uint32_t a1, uint32_t a2, uint32_t a3, uint32_t b0, uint32_t b1)
{
    asm volatile("mma.sync.aligned.m16n8k8.row.col.f32.tf32.tf32.f32 "
        "{%0,%1,%2,%3}, {%4,%5,%6,%7}, {%8,%9}, {%0,%1,%2,%3};"
        : "+f"(c[0]), "+f"(c[1]), "+f"(c[2]), "+f"(c[3])
        : "r"(a0), "r"(a1), "r"(a2), "r"(a3), "r"(b0), "r"(b1));
}
__device__ __forceinline__ uint32_t smem_u32(const void* p){
    return (uint32_t)__cvta_generic_to_shared(p);
}

// ---------------- weight convert ----------------
__global__ void cvtW_k(const float* __restrict__ src, uint32_t* __restrict__ dst,
                       int rows, int N, int ldd)
{
    int i = blockIdx.x*256 + threadIdx.x;
    if(i >= rows*ldd) return;
    int k = i / ldd, n = i % ldd;
    dst[i] = (n < N) ? f2tf32(src[(size_t)k*N + n]) : 0u;
}
__global__ void zero_stats5_k(){
    int i = blockIdx.x*256 + threadIdx.x;
    if(i < 5*SFD){ g_ssum5[i]=0.f; g_ssq5[i]=0.f; }
}

// ============================================================================
// tf32 tensor-core GEMM — R10 mainloop (locked). AH: A in fp16. CH: C (and
// res) in fp16. BN affine in-prologue; STATS from fp32 accumulators.
// ============================================================================
template<int TRANS, int STATS, int AH, int CH>
__global__ __launch_bounds__(256)
void gemm_tc(const void* __restrict__ Av, const uint32_t* __restrict__ B,
             void* __restrict__ Cv, int M, int K, int N, int ldb,
             const float* __restrict__ ssum, const float* __restrict__ ssq,
             const float* __restrict__ gamma, const float* __restrict__ gbeta,
             int Mstat,
             float* __restrict__ sumo, float* __restrict__ ssqo,
             const float* __restrict__ prw, const float* __restrict__ bias,
             const void* __restrict__ resv)
{
    const int BM=128, BN=128, BK=16;
    const int SA=20, SB=136;
    __shared__ uint32_t As[2][BM*SA];
    __shared__ uint32_t Bs[2][BK*SB];
    __shared__ float scol[BN], sqcol[BN];
    __shared__ float salpha[SFD], sbeta[SFD];

    int tid  = threadIdx.x;
    int wid  = tid >> 5, lane = tid & 31;
    int q    = lane & 3, g = lane >> 2;
    int wm   = (wid >> 2) * 64;
    int wn   = (wid & 3) * 32;
    int row0 = blockIdx.x * BM;
    int col0 = blockIdx.y * BN;
    float pw = (TRANS==2) ? __ldg(prw) : 0.f;

    float invM = 1.f / (float)Mstat;
    for(int k = tid; k < K; k += 256){
        float m = ssum[k]*invM;
        float v = ssq[k]*invM - m*m;
        float al = gamma[k]*rsqrtf(v + 1e-5f);
        salpha[k] = al;
        sbeta[k]  = gbeta[k] - m*al;
    }
    if(STATS && tid < BN){ scol[tid]=0.f; sqcol[tid]=0.f; }

    float acc[4][4][4];
#pragma unroll
    for(int mi=0;mi<4;mi++)
#pragma unroll
        for(int ni=0;ni<4;ni++)
#pragma unroll
            for(int j=0;j<4;j++) acc[mi][ni][j]=0.f;

    // A staging
    float4 ra[2];      // AH=0
    uint4  rah;        // AH=1: 8 halves
    int ar[2], ac[2], bk[2], bn[2];
    int ar1 = tid >> 1, ac1 = (tid & 1) << 3;     // AH=1 coords
#pragma unroll
    for(int i=0;i<2;i++){
        int idx = tid + i*256;
        ar[i] = idx >> 2;  ac[i] = (idx & 3) << 2;
        bk[i] = idx >> 5;  bn[i] = (idx & 31) << 2;
    }

    auto ldA = [&](int k0){
        if(AH){
            int grow = row0 + ar1;
            if(grow < M) rah = *(const uint4*)((const __half*)Av + (size_t)grow*K + k0 + ac1);
            else rah = make_uint4(0,0,0,0);
        } else {
#pragma unroll
            for(int i=0;i<2;i++){
                int grow = row0 + ar[i];
                ra[i] = (grow < M) ? *(const float4*)((const float*)Av + (size_t)grow*K + k0 + ac[i])
                                   : make_float4(0.f,0.f,0.f,0.f);
            }
        }
    };
    auto cpB = [&](int buf, int k0){
#pragma unroll
        for(int i=0;i<2;i++){
            const uint32_t* src = B + (size_t)(k0 + bk[i])*ldb + col0 + bn[i];
            uint32_t daddr = smem_u32(&Bs[buf][bk[i]*SB + bn[i]]);
            asm volatile("cp.async.ca.shared.global [%0], [%1], 16;\n"
                         :: "r"(daddr), "l"(src));
        }
        asm volatile("cp.async.commit_group;\n");
    };
    auto stA = [&](int buf, int k0){
        if(AH){
            float v[8];
            const uint32_t* ph = &rah.x;
#pragma unroll
            for(int j=0;j<4;j++){
                float2 f = __half22float2(*(__half2*)&ph[j]);
                v[2*j] = f.x; v[2*j+1] = f.y;
            }
            uint4 o0, o1;
            uint32_t* po0 = &o0.x; uint32_t* po1 = &o1.x;
#pragma unroll
            for(int j=0;j<8;j++){
                int gk = k0 + ac1 + j;
                float vv = fmaf(salpha[gk], v[j], sbeta[gk]);
                if(TRANS==2) vv = vv >= 0.f ? vv : pw*vv;
                uint32_t t = f2tf32(vv);
                if(j<4) po0[j] = t; else po1[j-4] = t;
            }
            *(uint4*)&As[buf][ar1*SA + ac1    ] = o0;
            *(uint4*)&As[buf][ar1*SA + ac1 + 4] = o1;
        } else {
#pragma unroll
            for(int i=0;i<2;i++){
                float v[4] = {ra[i].x, ra[i].y, ra[i].z, ra[i].w};
                uint4 o;
                uint32_t* po = &o.x;
#pragma unroll
                for(int j=0;j<4;j++){
                    int gk = k0 + ac[i] + j;
                    float vv = fmaf(salpha[gk], v[j], sbeta[gk]);
                    if(TRANS==2) vv = vv >= 0.f ? vv : pw*vv;
                    po[j] = f2tf32(vv);
                }
                *(uint4*)&As[buf][ar[i]*SA + ac[i]] = o;
            }
        }
    };

    ldA(0);
    cpB(0, 0);
    __syncthreads();

    int nIter = K / BK;
    for(int it=0; it<nIter; it++){
        int buf = it & 1;
        stA(buf, it*BK);
        if(it+1 < nIter) ldA((it+1)*BK);
        asm volatile("cp.async.wait_group 0;\n");
        __syncthreads();
        if(it+1 < nIter) cpB(buf^1, (it+1)*BK);
        const uint32_t* as = As[buf];
        const uint32_t* bs = Bs[buf];
#pragma unroll
        for(int s=0;s<2;s++){
            uint32_t af[4][4];
#pragma unroll
            for(int mi=0;mi<4;mi++){
                int base = wm + mi*16 + g;
                af[mi][0] = as[ base   *SA + s*8 + q    ];
                af[mi][1] = as[(base+8)*SA + s*8 + q    ];
                af[mi][2] = as[ base   *SA + s*8 + q + 4];
                af[mi][3] = as[(base+8)*SA + s*8 + q + 4];
            }
            uint32_t bf[4][2];
#pragma unroll
            for(int ni=0;ni<4;ni++){
                int n = wn + ni*8 + g;
                bf[ni][0] = bs[(s*8 + q    )*SB + n];
                bf[ni][1] = bs[(s*8 + q + 4)*SB + n];
            }
#pragma unroll
            for(int mi=0;mi<4;mi++)
#pragma unroll
                for(int ni=0;ni<4;ni++)
                    mma_tf32(acc[mi][ni], af[mi][0], af[mi][1], af[mi][2], af[mi][3],
                             bf[ni][0], bf[ni][1]);
        }
        __syncthreads();
    }

    // ---- epilogue ----
#pragma unroll
    for(int ni=0; ni<4; ni++){
        int cg = col0 + wn + ni*8 + 2*q;
        if(cg >= N) continue;
        float b0v = bias ? bias[cg]   : 0.f;
        float b1v = bias ? bias[cg+1] : 0.f;
        float s0=0.f,s1=0.f,q0=0.f,q1=0.f;
#pragma unroll
        for(int mi=0; mi<4; mi++){
            int r0 = row0 + wm + mi*16 + g;
#pragma unroll
            for(int h=0; h<2; h++){
                int r = r0 + h*8;
                if(r >= M) continue;
                float v0 = acc[mi][ni][h*2+0] + b0v;
                float v1 = acc[mi][ni][h*2+1] + b1v;
                if(resv){
                    float2 rf;
                    if(CH){
                        __half2 rr = *(const __half2*)((const __half*)resv + (size_t)r*N + cg);
                        rf = __half22float2(rr);
                    } else {
                        rf = *(const float2*)((const float*)resv + (size_t)r*N + cg);
                    }
                    v0 = (v0 + rf.x)*0.5f;
                    v1 = (v1 + rf.y)*0.5f;
                }
                if(CH){
                    __half2 hw = __floats2half2_rn(v0, v1);
                    *(__half2*)((__half*)Cv + (size_t)r*N + cg) = hw;
                } else {
                    float2 w; w.x=v0; w.y=v1;
                    *(float2*)((float*)Cv + (size_t)r*N + cg) = w;
                }
                if(STATS){
                    s0 += v0; s1 += v1;
                    q0 = fmaf(v0,v0,q0); q1 = fmaf(v1,v1,q1);
                }
            }
        }
        if(STATS){
            int lc = wn + ni*8 + 2*q;
            atomicAdd(&scol[lc],   s0); atomicAdd(&sqcol[lc],   q0);
            atomicAdd(&scol[lc+1], s1); atomicAdd(&sqcol[lc+1], q1);
        }
    }
    if(STATS){
        __syncthreads();
        if(tid < BN && col0 + tid < N){
            atomicAdd(&sumo[col0+tid], scol[tid]);
            atomicAdd(&ssqo[col0+tid], sqcol[tid]);
        }
    }
}

// ---------------- fp32 GEMM for xuv ----------------
__global__ __launch_bounds__(256)
void gemm_xuv_k(const float* __restrict__ A, const float* __restrict__ Wu,
                const float* __restrict__ Wv, float* __restrict__ C, int M)
{
    const int BM=128, BN=64, BK=16, K=64, LDC=128;
    const float* B = (blockIdx.y == 0) ? Wu : Wv;
    __shared__ float As[BK][BM];
    __shared__ float Bs[BK][BN];
    int tid = threadIdx.x;
    int tx = tid & 15;
    int ty = tid >> 4;
    int row0 = blockIdx.x * BM;
    int cout0 = blockIdx.y * BN;
    float acc[8][4];
#pragma unroll
    for(int i=0;i<8;i++)
#pragma unroll
        for(int j=0;j<4;j++) acc[i][j]=0.f;

    for(int k0=0;k0<K;k0+=BK){
#pragma unroll
        for(int l=tid; l<512; l+=256){
            int r  = l >> 2;
            int c4 = (l & 3) << 2;
            int grow = row0 + r;
            float4 v = make_float4(0.f,0.f,0.f,0.f);
            if(grow < M) v = *(const float4*)(A + (size_t)grow*K + k0 + c4);
            As[c4  ][r]=v.x; As[c4+1][r]=v.y; As[c4+2][r]=v.z; As[c4+3][r]=v.w;
        }
        {
            int r  = tid >> 4;
            int c4 = (tid & 15) << 2;
            float4 v = *(const float4*)(B + (size_t)(k0+r)*64 + c4);
            *(float4*)(&Bs[r][c4]) = v;
        }
        __syncthreads();
#pragma unroll
        for(int k=0;k<BK;k++){
            float4 a0 = *(const float4*)(&As[k][ty*8]);
            float4 a1 = *(const float4*)(&As[k][ty*8+4]);
            float4 b0 = *(const float4*)(&Bs[k][tx*4]);
            float am[8] = {a0.x,a0.y,a0.z,a0.w,a1.x,a1.y,a1.z,a1.w};
            float bn[4] = {b0.x,b0.y,b0.z,b0.w};
#pragma unroll
            for(int i=0;i<8;i++)
#pragma unroll
                for(int j=0;j<4;j++) acc[i][j]=fmaf(am[i],bn[j],acc[i][j]);
        }
        __syncthreads();
    }
    int cbase = cout0 + tx*4;
#pragma unroll
    for(int i=0;i<8;i++){
        int r = row0 + ty*8 + i;
        if(r >= M) break;
        float4 v;
        v.x = acc[i][0]; v.y = acc[i][1]; v.z = acc[i][2]; v.w = acc[i][3];
        *(float4*)(C + (size_t)r*LDC + cbase) = v;
    }
}

// ---------------- ea (8 threads/edge, fp32 output) ----------------
__global__ void ea_kernel(const float* __restrict__ xuv,
                          const float* __restrict__ eattr, const float* __restrict__ We,
                          const int* __restrict__ ei0, const int* __restrict__ ei1,
                          float* __restrict__ ea, int E)
{
    __shared__ float4 sW[16*16];
    for(int i=threadIdx.x;i<256;i+=256) sW[i] = ((const float4*)We)[i];
    __syncthreads();
    int e = (blockIdx.x*256 + threadIdx.x) >> 3;
    int h = threadIdx.x & 7;
    if(e >= E) return;
    int u = ei0[e], v = ei1[e];
    const float4* xv4 = (const float4*)xuv;
    float4 a0 = xv4[(size_t)u*32 + 2*h];
    float4 a1 = xv4[(size_t)u*32 + 2*h+1];
    float4 b0 = xv4[(size_t)v*32 + 16 + 2*h];
    float4 b1 = xv4[(size_t)v*32 + 16 + 2*h+1];
    float4 acc0, acc1;
    acc0.x=a0.x+b0.x; acc0.y=a0.y+b0.y; acc0.z=a0.z+b0.z; acc0.w=a0.w+b0.w;
    acc1.x=a1.x+b1.x; acc1.y=a1.y+b1.y; acc1.z=a1.z+b1.z; acc1.w=a1.w+b1.w;
    float w0 = eattr[(size_t)e*16 + h];
    float w1 = eattr[(size_t)e*16 + 8 + h];
    int lanebase = (threadIdx.x & 31) & ~7;
#pragma unroll
    for(int j=0;j<16;j++){
        float wj = __shfl_sync(0xffffffffu, (j<8)? w0 : w1, lanebase + (j & 7));
        float4 r0 = sW[j*16 + 2*h];
        float4 r1 = sW[j*16 + 2*h+1];
        acc0.x = fmaf(wj, r0.x, acc0.x); acc0.y = fmaf(wj, r0.y, acc0.y);
        acc0.z = fmaf(wj, r0.z, acc0.z); acc0.w = fmaf(wj, r0.w, acc0.w);
        acc1.x = fmaf(wj, r1.x, acc1.x); acc1.y = fmaf(wj, r1.y, acc1.y);
        acc1.z = fmaf(wj, r1.z, acc1.z); acc1.w = fmaf(wj, r1.w, acc1.w);
    }
    const float th = 1.f/3.f;
    acc0.x*=th; acc0.y*=th; acc0.z*=th; acc0.w*=th;
    acc1.x*=th; acc1.y*=th; acc1.z*=th; acc1.w*=th;
    float4* po = (float4*)(ea + (size_t)e*FD);
    po[2*h] = acc0; po[2*h+1] = acc1;
}

// ---------------- generic CSR build ----------------
__global__ void hist_k(const int* __restrict__ key, int* __restrict__ counts, int n){
    int i = blockIdx.x*256 + threadIdx.x;
    if(i < n) atomicAdd(&counts[key[i]], 1);
}
__global__ void scan1_k(const int* __restrict__ counts, int* __restrict__ offsets, int n){
    __shared__ int sh[1024];
    int tid = threadIdx.x;
    int i = blockIdx.x*1024 + tid;
    int v = (i<n) ? counts[i] : 0;
    sh[tid]=v; __syncthreads();
    for(int off=1; off<1024; off<<=1){
        int t = (tid>=off) ? sh[tid-off] : 0;
        __syncthreads();
        if(tid>=off) sh[tid]+=t;
        __syncthreads();
    }
    if(i<n) offsets[i] = sh[tid]-v;
    if(tid==1023) g_bsum[blockIdx.x]=sh[1023];
}
__global__ void scan2_k(int nb){
    __shared__ int sh[512];
    int tid = threadIdx.x;
    int v = (tid<nb)? g_bsum[tid] : 0;
    sh[tid]=v; __syncthreads();
    for(int off=1; off<512; off<<=1){
        int t = (tid>=off) ? sh[tid-off] : 0;
        __syncthreads();
        if(tid>=off) sh[tid]+=t;
        __syncthreads();
    }
    if(tid<nb) g_bsum[tid] = sh[tid]-v;
}
__global__ void scan3_k(int* __restrict__ offsets, int n, int total){
    int i = blockIdx.x*1024 + threadIdx.x;
    if(i<n) offsets[i] += g_bsum[blockIdx.x];
    if(i==0) offsets[n] = total;
}
__global__ void fill_k(const int* __restrict__ key, const int* __restrict__ src,
                       int* __restrict__ cursor, int* __restrict__ idx, int n){
    int i = blockIdx.x*256 + threadIdx.x;
    if(i < n){
        int d = key[i];
        int p = atomicAdd(&cursor[d], 1);
        idx[p] = src ? src[i] : i;
    }
}
__global__ void segstart_k(const int* __restrict__ batch, int E){
    int b = threadIdx.x;
    if(b > NBD) return;
    int lo=0, hi=E;
    while(lo<hi){ int mid=(lo+hi)>>1; if(batch[mid] < b) lo=mid+1; else hi=mid; }
    g_segstart[b]=lo;
}

// ---------------- message passing (8 thr/edge; HP selects prev type) -------
template<int HP>
__global__ void msgpass_k(const void* __restrict__ prevv, __half* __restrict__ out,
                          const float* __restrict__ ea, const float* __restrict__ gatW,
                          float* __restrict__ xw, int E)
{
    int e = (blockIdx.x*256 + threadIdx.x) >> 3;
    int h = threadIdx.x & 7;
    if(e >= E) return;
    const float4* pe = (const float4*)(ea + (size_t)e*FD);
    float4 A0 = pe[2*h], A1 = pe[2*h+1];
    float a0=A0.x,a1=A0.y,a2=A0.z,a3=A0.w,a4=A1.x,a5=A1.y,a6=A1.z,a7=A1.w;
    int s = g_offsets[e], t = g_offsets[e+1];
    for(int k=s;k<t;k++){
        int i0 = g_idx[k];
        if(HP){
            uint4 u = ((const uint4*)((const __half*)prevv + (size_t)i0*FD))[h];
            float2 f0 = __half22float2(*(__half2*)&u.x);
            float2 f1 = __half22float2(*(__half2*)&u.y);
            float2 f2 = __half22float2(*(__half2*)&u.z);
            float2 f3 = __half22float2(*(__half2*)&u.w);
            a0+=f0.x; a1+=f0.y; a2+=f1.x; a3+=f1.y;
            a4+=f2.x; a5+=f2.y; a6+=f3.x; a7+=f3.y;
        } else {
            const float4* pr = (const float4*)((const float*)prevv + (size_t)i0*FD);
            float4 v0 = pr[2*h], v1 = pr[2*h+1];
            a0+=v0.x; a1+=v0.y; a2+=v0.z; a3+=v0.w;
            a4+=v1.x; a5+=v1.y; a6+=v1.z; a7+=v1.w;
        }
    }
    __half2 o0 = __floats2half2_rn(a0,a1);
    __half2 o1 = __floats2half2_rn(a2,a3);
    __half2 o2 = __floats2half2_rn(a4,a5);
    __half2 o3 = __floats2half2_rn(a6,a7);
    uint4 w;
    w.x = *(uint32_t*)&o0; w.y = *(uint32_t*)&o1;
    w.z = *(uint32_t*)&o2; w.w = *(uint32_t*)&o3;
    ((uint4*)(out + (size_t)e*FD))[h] = w;
    const float4* gw4 = (const float4*)gatW;
    float4 g0 = gw4[2*h], g1 = gw4[2*h+1];
    float d = a0*g0.x + a1*g0.y + a2*g0.z + a3*g0.w
            + a4*g1.x + a5*g1.y + a6*g1.z + a7*g1.w;
#pragma unroll
    for(int o=4;o;o>>=1) d += __shfl_xor_sync(0xffffffffu, d, o);
    if(h==0) xw[e] = d;
}

// ---------------- GAT edge softmax -> xc ----------------
__device__ __forceinline__ float leaky02(float v){ return v >= 0.f ? v : 0.2f*v; }
__global__ void xc_k(const float* __restrict__ asrc, const float* __restrict__ adst,
                     const float* __restrict__ gbias, const float* __restrict__ xw, int E)
{
    int e = blockIdx.x*256 + threadIdx.x;
    if(e >= E) return;
    float as_ = __ldg(asrc), ad_ = __ldg(adst);
    float xwe = xw[e];
    float adv = xwe * ad_;
    int s = g_offsets[e], t = g_offsets[e+1];
    float m = leaky02(xwe*as_ + adv);
    for(int k=s;k<t;k++){
        float v = leaky02(xw[g_idx[k]]*as_ + adv);
        m = fmaxf(m, v);
    }
    float sum = expf(leaky02(xwe*as_ + adv) - m);
    float num = sum * xwe;
    for(int k=s;k<t;k++){
        float xws = xw[g_idx[k]];
        float ee = expf(leaky02(xws*as_ + adv) - m);
        sum += ee; num = fmaf(ee, xws, num);
    }
    g_xc[e] = num/(sum + 1e-16f) + __ldg(gbias);
}

// ---------------- attention pool: phase 1 ----------------
__global__ void pool1_k()
{
    __shared__ float sh[256];
    int b = blockIdx.x, tid = threadIdx.x;
    int s = g_segstart[b], t = g_segstart[b+1];
    float m = -3.4e38f;
    for(int i=s+tid;i<t;i+=256) m = fmaxf(m, g_xc[i]);
    sh[tid]=m; __syncthreads();
    for(int o=128;o;o>>=1){ if(tid<o) sh[tid]=fmaxf(sh[tid],sh[tid+o]); __syncthreads(); }
    float mm = sh[0]; __syncthreads();
    float ss = 0.f;
    for(int i=s+tid;i<t;i+=256) ss += expf(g_xc[i]-mm);
    sh[tid]=ss; __syncthreads();
    for(int o=128;o;o>>=1){ if(tid<o) sh[tid]+=sh[tid+o]; __syncthreads(); }
    if(tid==0){ g_pm[b]=mm; g_pd[b]=sh[0]+1e-16f; }
    if(tid < 64) g_gout[b*FD+tid] = 0.f;
}

// ---------------- attention pool: phase 2 (8 blocks/batch, fp16 out) -------
__global__ void pool2_k(const __half* __restrict__ out_t)
{
    __shared__ float sh[256];
    int b = blockIdx.x >> 3, chunk = blockIdx.x & 7;
    int tid = threadIdx.x;
    int s = g_segstart[b], t = g_segstart[b+1];
    float mm = g_pm[b], inv = 1.f/g_pd[b];
    int c = tid & 63, grp = tid >> 6;
    float acc = 0.f;
    for(int i = s + chunk*4 + grp; i < t; i += 32){
        float w = expf(g_xc[i]-mm);
        acc = fmaf(__half2float(out_t[(size_t)i*FD + c]), w, acc);
    }
    sh[tid]=acc; __syncthreads();
    if(tid < 64){
        float v = (sh[tid]+sh[64+tid]+sh[128+tid]+sh[192+tid]) * inv;
        atomicAdd(&g_gout[b*FD+tid], v);
    }
}

// ---------------- gt = tanh(gout @ Wg + bg) ----------------
__global__ void gt_k(const float* __restrict__ Wg, const float* __restrict__ bg,
                     float* __restrict__ gt)
{
    __shared__ float sg[64];
    int b = blockIdx.x, f = threadIdx.x;
    sg[f] = g_gout[b*FD+f]; __syncthreads();
    float acc = 0.f;
#pragma unroll 8
    for(int c=0;c<64;c++) acc = fmaf(sg[c], Wg[c*64+f], acc);
    gt[b*FD+f] = tanhf(acc + bg[f]);
}

__global__ void scatt_k(const float* __restrict__ a, const float* __restrict__ abias)
{
    int b = blockIdx.x, lane = threadIdx.x;
    float l0=0.f,l1=0.f,l2=0.f;
    for(int f=lane; f<64; f+=32){
        float g0 = g_gt[0*NBD*FD + b*FD + f];
        float g1 = g_gt[1*NBD*FD + b*FD + f];
        float g2 = g_gt[2*NBD*FD + b*FD + f];
        l0 = fmaf(g0, a[f*3+0], l0);
        l1 = fmaf(g1, a[f*3+1], l1);
        l2 = fmaf(g2, a[f*3+2], l2);
    }
#pragma unroll
    for(int o=16;o;o>>=1){
        l0 += __shfl_xor_sync(0xffffffffu,l0,o);
        l1 += __shfl_xor_sync(0xffffffffu,l1,o);
        l2 += __shfl_xor_sync(0xffffffffu,l2,o);
    }
    if(lane==0){
        l0 += abias[0]; l1 += abias[1]; l2 += abias[2];
        float m = fmaxf(l0, fmaxf(l1,l2));
        float e0 = expf(l0-m), e1 = expf(l1-m), e2 = expf(l2-m);
        float inv = 1.f/(e0+e1+e2);
        g_scatt[b*3+0]=e0*inv; g_scatt[b*3+1]=e1*inv; g_scatt[b*3+2]=e2*inv;
    }
}

// ---------------- xn = x + gather(mixed fp16 out), fused lin1 stats --------
__global__ void xnmix_k(const float* __restrict__ x,
                        const __half* __restrict__ o0, const __half* __restrict__ o1,
                        const __half* __restrict__ o2, const int* __restrict__ batch,
                        float* __restrict__ xn, int N)
{
    __shared__ float ssm[FD], ssq[FD];
    int tid = threadIdx.x;
    if(tid < FD){ ssm[tid]=0.f; ssq[tid]=0.f; }
    __syncthreads();
    int n = (blockIdx.x*256 + tid) >> 3;
    int h = tid & 7;
    float a[8];
    if(n < N){
        const float4* px = (const float4*)(x + (size_t)n*FD);
        float4 X0 = px[2*h], X1 = px[2*h+1];
        a[0]=X0.x; a[1]=X0.y; a[2]=X0.z; a[3]=X0.w;
        a[4]=X1.x; a[5]=X1.y; a[6]=X1.z; a[7]=X1.w;
        int s = g_noffsets[n], t = g_noffsets[n+1];
        for(int k=s;k<t;k++){
            int e = g_nidx[k];
            int b = batch[e];
            float w0 = g_scatt[b*3], w1 = g_scatt[b*3+1], w2 = g_scatt[b*3+2];
            uint4 u0 = ((const uint4*)(o0 + (size_t)e*FD))[h];
            uint4 u1 = ((const uint4*)(o1 + (size_t)e*FD))[h];
            uint4 u2 = ((const uint4*)(o2 + (size_t)e*FD))[h];
            const uint32_t* p0 = &u0.x;
            const uint32_t* p1 = &u1.x;
            const uint32_t* p2 = &u2.x;
#pragma unroll
            for(int j=0;j<4;j++){
                float2 f0 = __half22float2(*(__half2*)&p0[j]);
                float2 f1 = __half22float2(*(__half2*)&p1[j]);
                float2 f2 = __half22float2(*(__half2*)&p2[j]);
                a[2*j  ] += f0.x*w0 + f1.x*w1 + f2.x*w2;
                a[2*j+1] += f0.y*w0 + f1.y*w1 + f2.y*w2;
            }
        }
        float4 W0, W1;
        W0.x=a[0]; W0.y=a[1]; W0.z=a[2]; W0.w=a[3];
        W1.x=a[4]; W1.y=a[5]; W1.z=a[6]; W1.w=a[7];
        float4* po = (float4*)(xn + (size_t)n*FD);
        po[2*h] = W0; po[2*h+1] = W1;
        int c0 = h*8;
#pragma unroll
        for(int j=0;j<8;j++){
            atomicAdd(&ssm[c0+j], a[j]);
            atomicAdd(&ssq[c0+j], a[j]*a[j]);
        }
    }
    __syncthreads();
    if(tid < FD){
        atomicAdd(&g_ssum5[tid], ssm[tid]);
        atomicAdd(&g_ssq5[tid],  ssq[tid]);
    }
}

// ---------------- host ----------------
extern "C" void kernel_launch(void* const* d_in, const int* in_sizes, int n_in,
                              void* d_out, int out_size)
{
    bool setupOrder = (in_sizes[2] > 100000);
    int IX, IEA, IEI, ILG, IBATCH, IWU, IWV, IWE, IGW, IAS, IAD, IGB, IA, IAB, IWG, IBG;
    int IB1G, IB1B, IW1, Ib1, IBNG, IBNB, IPR, IW, Ib, IB5G, IB5B, IPR5, IW5, Ib5;
    if(setupOrder){
        IX=0; IEA=1; IEI=2; ILG=3; IBATCH=4; IWU=5; IWV=6; IWE=7; IGW=8; IAS=9; IAD=10; IGB=11;
        IA=12; IAB=13; IWG=14; IBG=15; IB1G=16; IB1B=17; IW1=18; Ib1=19; IBNG=20; IBNB=21;
        IPR=22; IW=23; Ib=24; IB5G=25; IB5B=26; IPR5=27; IW5=28; Ib5=29;
    } else {
        IX=0; IEA=1; IWU=2; IWV=3; IWE=4; IGW=5; IAS=6; IAD=7; IGB=8; IA=9; IAB=10; IWG=11; IBG=12;
        IB1G=13; IB1B=14; IW1=15; Ib1=16; IBNG=17; IBNB=18; IPR=19; IW=20; Ib=21;
        IB5G=22; IB5B=23; IPR5=24; IW5=25; Ib5=26; IEI=27; ILG=28; IBATCH=29;
    }
    const float* x     = (const float*)d_in[IX];
    const float* eattr = (const float*)d_in[IEA];
    const int*   ei    = (const int*)d_in[IEI];
    const int*   lg    = (const int*)d_in[ILG];
    const int*   batch = (const int*)d_in[IBATCH];
    const float* W_u = (const float*)d_in[IWU];
    const float* W_v = (const float*)d_in[IWV];
    const float* W_e = (const float*)d_in[IWE];
    const float* gatW = (const float*)d_in[IGW];
    const float* asrc = (const float*)d_in[IAS];
    const float* adst = (const float*)d_in[IAD];
    const float* gbias = (const float*)d_in[IGB];
    const float* a_att = (const float*)d_in[IA];
    const float* a_bias = (const float*)d_in[IAB];
    const float* W_gout = (const float*)d_in[IWG];
    const float* b_gout = (const float*)d_in[IBG];
    const float* bn1g = (const float*)d_in[IB1G];
    const float* bn1b = (const float*)d_in[IB1B];
    const float* W1 = (const float*)d_in[IW1];
    const float* b1 = (const float*)d_in[Ib1];
    const float* bng = (const float*)d_in[IBNG];
    const float* bnb = (const float*)d_in[IBNB];
    const float* pr  = (const float*)d_in[IPR];
    const float* Wm  = (const float*)d_in[IW];
    const float* bm  = (const float*)d_in[Ib];
    const float* bn5g = (const float*)d_in[IB5G];
    const float* bn5b = (const float*)d_in[IB5B];
    const float* pr5 = (const float*)d_in[IPR5];
    const float* W5 = (const float*)d_in[IW5];
    const float* b5 = (const float*)d_in[Ib5];

    const int N  = in_sizes[IX] / FD;
    const int E  = in_sizes[IEA] / 16;
    const int LE = in_sizes[ILG] / 2;
    const int* ei0 = ei;       const int* ei1 = ei + E;
    const int* lg0 = lg;       const int* lg1 = lg + LE;

    void *p;
    float *xuv_p, *ea_p, *xn_p, *gt_p, *xw_p;
    float *ssum5_p, *ssq5_p;
    __half *outh_p, *bufA, *bufB, *bufC;
    int *counts_p, *offsets_p, *cursor_p, *ncounts_p, *noffsets_p, *ncursor_p, *nidx_p, *idx_p;
    uint32_t *w1t, *wmt, *w5t;
    cudaGetSymbolAddress(&p, g_xuv);    xuv_p=(float*)p;
    cudaGetSymbolAddress(&p, g_ea);     ea_p=(float*)p;
    cudaGetSymbolAddress(&p, g_outh);   outh_p=(__half*)p;
    cudaGetSymbolAddress(&p, g_xn);     xn_p=(float*)p;
    cudaGetSymbolAddress(&p, g_bufA);   bufA=(__half*)p;
    cudaGetSymbolAddress(&p, g_bufB);   bufB=(__half*)p;
    cudaGetSymbolAddress(&p, g_bufC);   bufC=(__half*)p;
    cudaGetSymbolAddress(&p, g_gt);     gt_p=(float*)p;
    cudaGetSymbolAddress(&p, g_xw);     xw_p=(float*)p;
    cudaGetSymbolAddress(&p, g_ssum5);  ssum5_p=(float*)p;
    cudaGetSymbolAddress(&p, g_ssq5);   ssq5_p=(float*)p;
    cudaGetSymbolAddress(&p, g_counts); counts_p=(int*)p;
    cudaGetSymbolAddress(&p, g_offsets);offsets_p=(int*)p;
    cudaGetSymbolAddress(&p, g_cursor); cursor_p=(int*)p;
    cudaGetSymbolAddress(&p, g_ncounts); ncounts_p=(int*)p;
    cudaGetSymbolAddress(&p, g_noffsets);noffsets_p=(int*)p;
    cudaGetSymbolAddress(&p, g_ncursor); ncursor_p=(int*)p;
    cudaGetSymbolAddress(&p, g_nidx);    nidx_p=(int*)p;
    cudaGetSymbolAddress(&p, g_idx);     idx_p=(int*)p;
    cudaGetSymbolAddress(&p, g_W1t);    w1t=(uint32_t*)p;
    cudaGetSymbolAddress(&p, g_Wmt);    wmt=(uint32_t*)p;
    cudaGetSymbolAddress(&p, g_W5t);    w5t=(uint32_t*)p;

    static cudaStream_t s1 = nullptr;
    static cudaEvent_t ev0=nullptr, evCSR=nullptr, evNCSR=nullptr,
                       evM[NITD]={nullptr,nullptr,nullptr}, evScatt=nullptr, evCvt=nullptr;
    if(!s1){
        cudaStreamCreateWithFlags(&s1, cudaStreamNonBlocking);
        cudaEventCreateWithFlags(&ev0,    cudaEventDisableTiming);
        cudaEventCreateWithFlags(&evCSR,  cudaEventDisableTiming);
        cudaEventCreateWithFlags(&evNCSR, cudaEventDisableTiming);
        for(int t=0;t<NITD;t++) cudaEventCreateWithFlags(&evM[t], cudaEventDisableTiming);
        cudaEventCreateWithFlags(&evScatt,cudaEventDisableTiming);
        cudaEventCreateWithFlags(&evCvt,  cudaEventDisableTiming);
    }
    cudaStream_t s0 = 0;

    // ---- fork ----
    cudaEventRecord(ev0, s0);
    cudaStreamWaitEvent(s1, ev0, 0);

    // ===== s1: stats zero, weight conversion, line CSR, node CSR =====
    zero_stats5_k<<<cdiv(5*SFD,256),256,0,s1>>>();
    cvtW_k<<<cdiv(FD*SFD,256),256,0,s1>>>(W1, w1t, FD, SFD, SFD);
    cvtW_k<<<cdiv(3*SFD*SFD,256),256,0,s1>>>(Wm, wmt, 3*SFD, SFD, SFD);
    cvtW_k<<<cdiv(SFD*128,256),256,0,s1>>>(W5, w5t, SFD, FD, 128);
    cudaEventRecord(evCvt, s1);
    cudaMemsetAsync(counts_p, 0, (size_t)E*sizeof(int), s1);
    hist_k<<<cdiv(LE,256),256,0,s1>>>(lg1, counts_p, LE);
    int nblkE = cdiv(E,1024);
    scan1_k<<<nblkE,1024,0,s1>>>(counts_p, offsets_p, E);
    scan2_k<<<1,512,0,s1>>>(nblkE);
    scan3_k<<<nblkE,1024,0,s1>>>(offsets_p, E, LE);
    cudaMemcpyAsync(cursor_p, offsets_p, (size_t)E*sizeof(int), cudaMemcpyDeviceToDevice, s1);
    fill_k<<<cdiv(LE,256),256,0,s1>>>(lg1, lg0, cursor_p, idx_p, LE);
    segstart_k<<<1,NBD+1,0,s1>>>(batch, E);
    cudaEventRecord(evCSR, s1);
    cudaMemsetAsync(ncounts_p, 0, (size_t)N*sizeof(int), s1);
    hist_k<<<cdiv(E,256),256,0,s1>>>(ei1, ncounts_p, E);
    int nblkN = cdiv(N,1024);
    scan1_k<<<nblkN,1024,0,s1>>>(ncounts_p, noffsets_p, N);
    scan2_k<<<1,512,0,s1>>>(nblkN);
    scan3_k<<<nblkN,1024,0,s1>>>(noffsets_p, N, E);
    cudaMemcpyAsync(ncursor_p, noffsets_p, (size_t)N*sizeof(int), cudaMemcpyDeviceToDevice, s1);
    fill_k<<<cdiv(E,256),256,0,s1>>>(ei1, nullptr, ncursor_p, nidx_p, E);
    cudaEventRecord(evNCSR, s1);

    // ===== s0: xuv -> ea (fp32) =====
    gemm_xuv_k<<<dim3(cdiv(N,128),2),256,0,s0>>>(x, W_u, W_v, xuv_p, N);
    ea_kernel<<<cdiv(E,32),256,0,s0>>>(xuv_p, eattr, W_e, ei0, ei1, ea_p, E);

    // ===== iterations =====
    cudaStreamWaitEvent(s0, evCSR, 0);
    const size_t OSTRIDE = (size_t)MAXE*FD;
    for(int t=0;t<NITD;t++){
        __half* outt = outh_p + (size_t)t*OSTRIDE;
        float* xwt  = xw_p + (size_t)t*MAXE;
        if(t==0)
            msgpass_k<0><<<cdiv(E,32),256,0,s0>>>(ea_p, outt, ea_p, gatW, xwt, E);
        else
            msgpass_k<1><<<cdiv(E,32),256,0,s0>>>(outh_p + (size_t)(t-1)*OSTRIDE, outt,
                                                  ea_p, gatW, xwt, E);
        cudaEventRecord(evM[t], s0);
        cudaStreamWaitEvent(s1, evM[t], 0);
        xc_k<<<cdiv(E,256),256,0,s1>>>(asrc, adst, gbias, xwt, E);
        pool1_k<<<NBD,256,0,s1>>>();
        pool2_k<<<NBD*8,256,0,s1>>>(outt);
        gt_k<<<NBD,64,0,s1>>>(W_gout, b_gout, gt_p + (size_t)t*NBD*FD);
    }
    scatt_k<<<NBD,32,0,s1>>>(a_att, a_bias);
    cudaEventRecord(evScatt, s1);

    // ===== s0: xn (fused lin1 stats -> slot 0) -> LinearBlock =====
    cudaStreamWaitEvent(s0, evScatt, 0);
    cudaStreamWaitEvent(s0, evNCSR, 0);
    xnmix_k<<<cdiv(N,32),256,0,s0>>>(x, outh_p, outh_p+OSTRIDE, outh_p+2*OSTRIDE,
                                     batch, xn_p, N);

    cudaStreamWaitEvent(s0, evCvt, 0);
    // lin1: A fp32 (xn) -> C fp16 (bufA)
    gemm_tc<1,1,0,1><<<dim3(cdiv(N,128),SFD/128),256,0,s0>>>(xn_p, w1t, bufA, N, FD, SFD, SFD,
        ssum5_p, ssq5_p, bn1g, bn1b, N, ssum5_p+SFD, ssq5_p+SFD, nullptr, b1, nullptr);
    // lin2: fp16 -> fp16
    gemm_tc<2,1,1,1><<<dim3(cdiv(N,128),SFD/128),256,0,s0>>>(bufA, wmt, bufB, N, SFD, SFD, SFD,
        ssum5_p+SFD, ssq5_p+SFD, bng, bnb, N, ssum5_p+2*SFD, ssq5_p+2*SFD, pr, bm, nullptr);
    // lin3: fp16 -> fp16, res=bufA fp16
    gemm_tc<2,1,1,1><<<dim3(cdiv(N,128),SFD/128),256,0,s0>>>(bufB, wmt+(size_t)SFD*SFD, bufC, N, SFD, SFD, SFD,
        ssum5_p+2*SFD, ssq5_p+2*SFD, bng+SFD, bnb+SFD, N, ssum5_p+3*SFD, ssq5_p+3*SFD, pr+1, bm+SFD, bufA);
    // lin4: fp16 -> fp16, res=bufC fp16
    gemm_tc<2,1,1,1><<<dim3(cdiv(N,128),SFD/128),256,0,s0>>>(bufC, wmt+(size_t)2*SFD*SFD, bufA, N, SFD, SFD, SFD,
        ssum5_p+3*SFD, ssq5_p+3*SFD, bng+2*SFD, bnb+2*SFD, N, ssum5_p+4*SFD, ssq5_p+4*SFD, pr+2, bm+2*SFD, bufC);
    // lin5: A fp16 -> C fp32 (d_out)
    gemm_tc<2,0,1,0><<<dim3(cdiv(N,128),1),256,0,s0>>>(bufA, w5t, (float*)d_out, N, SFD, FD, 128,
        ssum5_p+4*SFD, ssq5_p+4*SFD, bn5g, bn5b, N, nullptr, nullptr, pr5, b5, nullptr);
}

// round 16
// speedup vs baseline: 1.0311x; 1.0311x over previous
#include <cuda_runtime.h>
#include <cuda_fp16.h>
#include <stdint.h>
#include <math.h>

#define FD   64
#define SFD  384
#define NITD 3
#define NBD  256
#define MAXN 50000
#define MAXE 400000
#define MAXLE 1600000

static inline int cdiv(int a, int b){ return (a + b - 1) / b; }

// ---------------- scratch ----------------
__device__ float  g_xuv[(size_t)MAXN*128];
__device__ float  g_ea[(size_t)MAXE*FD];           // fp32 ea
__device__ __half g_outh[NITD][(size_t)MAXE*FD];   // fp16 storage for out
__device__ int   g_counts[MAXE];
__device__ int   g_offsets[MAXE+1];
__device__ int   g_cursor[MAXE];
__device__ int   g_ncounts[MAXN];
__device__ int   g_noffsets[MAXN+1];
__device__ int   g_ncursor[MAXN];
__device__ int   g_nidx[MAXE];
__device__ int   g_bsum[1024];
__device__ int   g_idx[MAXLE];
__device__ float g_xw[NITD][MAXE];
__device__ float g_xc[MAXE];
__device__ int   g_segstart[NBD+1];
__device__ float g_pm[NBD];
__device__ float g_pd[NBD];
__device__ float g_gout[NBD*FD];
__device__ float g_gt[NITD*NBD*FD];
__device__ float g_scatt[NBD*NITD];
__device__ float g_xn[(size_t)MAXN*FD];
__device__ float g_bufA[(size_t)MAXN*SFD];
__device__ float g_bufB[(size_t)MAXN*SFD];
__device__ float g_bufC[(size_t)MAXN*SFD];
__device__ float g_ssum5[5*SFD];
__device__ float g_ssq5[5*SFD];
__device__ uint32_t g_W1t[FD*SFD];
__device__ uint32_t g_Wmt[3*SFD*SFD];
__device__ uint32_t g_W5t[SFD*128];

// ---------------- tf32 helpers ----------------
__device__ __forceinline__ uint32_t f2tf32(float v){
    uint32_t o; asm("cvt.rna.tf32.f32 %0, %1;" : "=r"(o) : "f"(v)); return o;
}
__device__ __forceinline__ void mma_tf32(float (&c)[4],
    uint32_t a0, uint32_t a1, uint32_t a2, uint32_t a3, uint32_t b0, uint32_t b1)
{
    asm volatile("mma.sync.aligned.m16n8k8.row.col.f32.tf32.tf32.f32 "
        "{%0,%1,%2,%3}, {%4,%5,%6,%7}, {%8,%9}, {%0,%1,%2,%3};"
        : "+f"(c[0]), "+f"(c[1]), "+f"(c[2]), "+f"(c[3])
        : "r"(a0), "r"(a1), "r"(a2), "r"(a3), "r"(b0), "r"(b1));
}
__device__ __forceinline__ uint32_t smem_u32(const void* p){
    return (uint32_t)__cvta_generic_to_shared(p);
}

// ---------------- weight convert ----------------
__global__ void cvtW_k(const float* __restrict__ src, uint32_t* __restrict__ dst,
                       int rows, int N, int ldd)
{
    int i = blockIdx.x*256 + threadIdx.x;
    if(i >= rows*ldd) return;
    int k = i / ldd, n = i % ldd;
    dst[i] = (n < N) ? f2tf32(src[(size_t)k*N + n]) : 0u;
}
__global__ void zero_stats5_k(){
    int i = blockIdx.x*256 + threadIdx.x;
    if(i < 5*SFD){ g_ssum5[i]=0.f; g_ssq5[i]=0.f; }
}

// ============================================================================
// tf32 tensor-core GEMM — EXACT R10/R12 structure. BN affine in-prologue.
// ============================================================================
template<int TRANS, int STATS>
__global__ __launch_bounds__(256)
void gemm_tc(const float* __restrict__ A, const uint32_t* __restrict__ B,
             float* __restrict__ C, int M, int K, int N, int ldb,
             const float* __restrict__ ssum, const float* __restrict__ ssq,
             const float* __restrict__ gamma, const float* __restrict__ gbeta,
             int Mstat,
             float* __restrict__ sumo, float* __restrict__ ssqo,
             const float* __restrict__ prw, const float* __restrict__ bias,
             const float* __restrict__ res)
{
    const int BM=128, BN=128, BK=16;
    const int SA=20, SB=136;
    __shared__ uint32_t As[2][BM*SA];
    __shared__ uint32_t Bs[2][BK*SB];
    __shared__ float scol[BN], sqcol[BN];
    __shared__ float salpha[SFD], sbeta[SFD];

    int tid  = threadIdx.x;
    int wid  = tid >> 5, lane = tid & 31;
    int q    = lane & 3, g = lane >> 2;
    int wm   = (wid >> 2) * 64;
    int wn   = (wid & 3) * 32;
    int row0 = blockIdx.x * BM;
    int col0 = blockIdx.y * BN;
    float pw = (TRANS==2) ? __ldg(prw) : 0.f;

    float invM = 1.f / (float)Mstat;
    for(int k = tid; k < K; k += 256){
        float m = ssum[k]*invM;
        float v = ssq[k]*invM - m*m;
        float al = gamma[k]*rsqrtf(v + 1e-5f);
        salpha[k] = al;
        sbeta[k]  = gbeta[k] - m*al;
    }
    if(STATS && tid < BN){ scol[tid]=0.f; sqcol[tid]=0.f; }

    float acc[4][4][4];
#pragma unroll
    for(int mi=0;mi<4;mi++)
#pragma unroll
        for(int ni=0;ni<4;ni++)
#pragma unroll
            for(int j=0;j<4;j++) acc[mi][ni][j]=0.f;

    float4 ra[2];
    int ar[2], ac[2], bk[2], bn[2];
#pragma unroll
    for(int i=0;i<2;i++){
        int idx = tid + i*256;
        ar[i] = idx >> 2;  ac[i] = (idx & 3) << 2;
        bk[i] = idx >> 5;  bn[i] = (idx & 31) << 2;
    }

    auto ldA = [&](int k0){
#pragma unroll
        for(int i=0;i<2;i++){
            int grow = row0 + ar[i];
            ra[i] = (grow < M) ? *(const float4*)(A + (size_t)grow*K + k0 + ac[i])
                               : make_float4(0.f,0.f,0.f,0.f);
        }
    };
    auto cpB = [&](int buf, int k0){
#pragma unroll
        for(int i=0;i<2;i++){
            const uint32_t* src = B + (size_t)(k0 + bk[i])*ldb + col0 + bn[i];
            uint32_t daddr = smem_u32(&Bs[buf][bk[i]*SB + bn[i]]);
            asm volatile("cp.async.ca.shared.global [%0], [%1], 16;\n"
                         :: "r"(daddr), "l"(src));
        }
        asm volatile("cp.async.commit_group;\n");
    };
    auto stA = [&](int buf, int k0){
#pragma unroll
        for(int i=0;i<2;i++){
            float v[4] = {ra[i].x, ra[i].y, ra[i].z, ra[i].w};
            uint4 o;
            uint32_t* po = &o.x;
#pragma unroll
            for(int j=0;j<4;j++){
                int gk = k0 + ac[i] + j;
                float vv = fmaf(salpha[gk], v[j], sbeta[gk]);
                if(TRANS==2) vv = vv >= 0.f ? vv : pw*vv;
                po[j] = f2tf32(vv);
            }
            *(uint4*)&As[buf][ar[i]*SA + ac[i]] = o;
        }
    };

    ldA(0);
    cpB(0, 0);
    __syncthreads();

    int nIter = K / BK;
    for(int it=0; it<nIter; it++){
        int buf = it & 1;
        stA(buf, it*BK);
        if(it+1 < nIter) ldA((it+1)*BK);
        asm volatile("cp.async.wait_group 0;\n");
        __syncthreads();
        if(it+1 < nIter) cpB(buf^1, (it+1)*BK);
        const uint32_t* as = As[buf];
        const uint32_t* bs = Bs[buf];
#pragma unroll
        for(int s=0;s<2;s++){
            uint32_t af[4][4];
#pragma unroll
            for(int mi=0;mi<4;mi++){
                int base = wm + mi*16 + g;
                af[mi][0] = as[ base   *SA + s*8 + q    ];
                af[mi][1] = as[(base+8)*SA + s*8 + q    ];
                af[mi][2] = as[ base   *SA + s*8 + q + 4];
                af[mi][3] = as[(base+8)*SA + s*8 + q + 4];
            }
            uint32_t bf[4][2];
#pragma unroll
            for(int ni=0;ni<4;ni++){
                int n = wn + ni*8 + g;
                bf[ni][0] = bs[(s*8 + q    )*SB + n];
                bf[ni][1] = bs[(s*8 + q + 4)*SB + n];
            }
#pragma unroll
            for(int mi=0;mi<4;mi++)
#pragma unroll
                for(int ni=0;ni<4;ni++)
                    mma_tf32(acc[mi][ni], af[mi][0], af[mi][1], af[mi][2], af[mi][3],
                             bf[ni][0], bf[ni][1]);
        }
        __syncthreads();
    }

#pragma unroll
    for(int ni=0; ni<4; ni++){
        int cg = col0 + wn + ni*8 + 2*q;
        if(cg >= N) continue;
        float b0v = bias ? bias[cg]   : 0.f;
        float b1v = bias ? bias[cg+1] : 0.f;
        float s0=0.f,s1=0.f,q0=0.f,q1=0.f;
#pragma unroll
        for(int mi=0; mi<4; mi++){
            int r0 = row0 + wm + mi*16 + g;
#pragma unroll
            for(int h=0; h<2; h++){
                int r = r0 + h*8;
                if(r >= M) continue;
                float v0 = acc[mi][ni][h*2+0] + b0v;
                float v1 = acc[mi][ni][h*2+1] + b1v;
                if(res){
                    float2 rr = *(const float2*)(res + (size_t)r*N + cg);
                    v0 = (v0 + rr.x)*0.5f;
                    v1 = (v1 + rr.y)*0.5f;
                }
                float2 w; w.x=v0; w.y=v1;
                *(float2*)(C + (size_t)r*N + cg) = w;
                if(STATS){
                    s0 += v0; s1 += v1;
                    q0 = fmaf(v0,v0,q0); q1 = fmaf(v1,v1,q1);
                }
            }
        }
        if(STATS){
            int lc = wn + ni*8 + 2*q;
            atomicAdd(&scol[lc],   s0); atomicAdd(&sqcol[lc],   q0);
            atomicAdd(&scol[lc+1], s1); atomicAdd(&sqcol[lc+1], q1);
        }
    }
    if(STATS){
        __syncthreads();
        if(tid < BN && col0 + tid < N){
            atomicAdd(&sumo[col0+tid], scol[tid]);
            atomicAdd(&ssqo[col0+tid], sqcol[tid]);
        }
    }
}

// ---------------- fp32 GEMM for xuv ----------------
__global__ __launch_bounds__(256)
void gemm_xuv_k(const float* __restrict__ A, const float* __restrict__ Wu,
                const float* __restrict__ Wv, float* __restrict__ C, int M)
{
    const int BM=128, BN=64, BK=16, K=64, LDC=128;
    const float* B = (blockIdx.y == 0) ? Wu : Wv;
    __shared__ float As[BK][BM];
    __shared__ float Bs[BK][BN];
    int tid = threadIdx.x;
    int tx = tid & 15;
    int ty = tid >> 4;
    int row0 = blockIdx.x * BM;
    int cout0 = blockIdx.y * BN;
    float acc[8][4];
#pragma unroll
    for(int i=0;i<8;i++)
#pragma unroll
        for(int j=0;j<4;j++) acc[i][j]=0.f;

    for(int k0=0;k0<K;k0+=BK){
#pragma unroll
        for(int l=tid; l<512; l+=256){
            int r  = l >> 2;
            int c4 = (l & 3) << 2;
            int grow = row0 + r;
            float4 v = make_float4(0.f,0.f,0.f,0.f);
            if(grow < M) v = *(const float4*)(A + (size_t)grow*K + k0 + c4);
            As[c4  ][r]=v.x; As[c4+1][r]=v.y; As[c4+2][r]=v.z; As[c4+3][r]=v.w;
        }
        {
            int r  = tid >> 4;
            int c4 = (tid & 15) << 2;
            float4 v = *(const float4*)(B + (size_t)(k0+r)*64 + c4);
            *(float4*)(&Bs[r][c4]) = v;
        }
        __syncthreads();
#pragma unroll
        for(int k=0;k<BK;k++){
            float4 a0 = *(const float4*)(&As[k][ty*8]);
            float4 a1 = *(const float4*)(&As[k][ty*8+4]);
            float4 b0 = *(const float4*)(&Bs[k][tx*4]);
            float am[8] = {a0.x,a0.y,a0.z,a0.w,a1.x,a1.y,a1.z,a1.w};
            float bn[4] = {b0.x,b0.y,b0.z,b0.w};
#pragma unroll
            for(int i=0;i<8;i++)
#pragma unroll
                for(int j=0;j<4;j++) acc[i][j]=fmaf(am[i],bn[j],acc[i][j]);
        }
        __syncthreads();
    }
    int cbase = cout0 + tx*4;
#pragma unroll
    for(int i=0;i<8;i++){
        int r = row0 + ty*8 + i;
        if(r >= M) break;
        float4 v;
        v.x = acc[i][0]; v.y = acc[i][1]; v.z = acc[i][2]; v.w = acc[i][3];
        *(float4*)(C + (size_t)r*LDC + cbase) = v;
    }
}

// ---------------- ea (8 threads/edge, float4) ----------------
__global__ void ea_kernel(const float* __restrict__ xuv,
                          const float* __restrict__ eattr, const float* __restrict__ We,
                          const int* __restrict__ ei0, const int* __restrict__ ei1,
                          float* __restrict__ ea, int E)
{
    __shared__ float4 sW[16*16];
    for(int i=threadIdx.x;i<256;i+=256) sW[i] = ((const float4*)We)[i];
    __syncthreads();
    int e = (blockIdx.x*256 + threadIdx.x) >> 3;
    int h = threadIdx.x & 7;
    if(e >= E) return;
    int u = ei0[e], v = ei1[e];
    const float4* xv4 = (const float4*)xuv;
    float4 a0 = xv4[(size_t)u*32 + h];
    float4 a1 = xv4[(size_t)u*32 + 8 + h];
    float4 b0 = xv4[(size_t)v*32 + 16 + h];
    float4 b1 = xv4[(size_t)v*32 + 24 + h];
    float4 acc0, acc1;
    acc0.x=a0.x+b0.x; acc0.y=a0.y+b0.y; acc0.z=a0.z+b0.z; acc0.w=a0.w+b0.w;
    acc1.x=a1.x+b1.x; acc1.y=a1.y+b1.y; acc1.z=a1.z+b1.z; acc1.w=a1.w+b1.w;
    float w0 = eattr[(size_t)e*16 + h];
    float w1 = eattr[(size_t)e*16 + 8 + h];
    int lanebase = (threadIdx.x & 31) & ~7;
#pragma unroll
    for(int j=0;j<16;j++){
        float wj = __shfl_sync(0xffffffffu, (j<8)? w0 : w1, lanebase + (j & 7));
        float4 r0 = sW[j*16 + h];
        float4 r1 = sW[j*16 + 8 + h];
        acc0.x = fmaf(wj, r0.x, acc0.x); acc0.y = fmaf(wj, r0.y, acc0.y);
        acc0.z = fmaf(wj, r0.z, acc0.z); acc0.w = fmaf(wj, r0.w, acc0.w);
        acc1.x = fmaf(wj, r1.x, acc1.x); acc1.y = fmaf(wj, r1.y, acc1.y);
        acc1.z = fmaf(wj, r1.z, acc1.z); acc1.w = fmaf(wj, r1.w, acc1.w);
    }
    const float th = 1.f/3.f;
    acc0.x*=th; acc0.y*=th; acc0.z*=th; acc0.w*=th;
    acc1.x*=th; acc1.y*=th; acc1.z*=th; acc1.w*=th;
    float4* po = (float4*)(ea + (size_t)e*FD);
    po[h] = acc0; po[8+h] = acc1;
}

// ---------------- generic CSR build ----------------
__global__ void hist_k(const int* __restrict__ key, int* __restrict__ counts, int n){
    int i = blockIdx.x*256 + threadIdx.x;
    if(i < n) atomicAdd(&counts[key[i]], 1);
}
__global__ void scan1_k(const int* __restrict__ counts, int* __restrict__ offsets, int n){
    __shared__ int sh[1024];
    int tid = threadIdx.x;
    int i = blockIdx.x*1024 + tid;
    int v = (i<n) ? counts[i] : 0;
    sh[tid]=v; __syncthreads();
    for(int off=1; off<1024; off<<=1){
        int t = (tid>=off) ? sh[tid-off] : 0;
        __syncthreads();
        if(tid>=off) sh[tid]+=t;
        __syncthreads();
    }
    if(i<n) offsets[i] = sh[tid]-v;
    if(tid==1023) g_bsum[blockIdx.x]=sh[1023];
}
__global__ void scan2_k(int nb){
    __shared__ int sh[512];
    int tid = threadIdx.x;
    int v = (tid<nb)? g_bsum[tid] : 0;
    sh[tid]=v; __syncthreads();
    for(int off=1; off<512; off<<=1){
        int t = (tid>=off) ? sh[tid-off] : 0;
        __syncthreads();
        if(tid>=off) sh[tid]+=t;
        __syncthreads();
    }
    if(tid<nb) g_bsum[tid] = sh[tid]-v;
}
__global__ void scan3_k(int* __restrict__ offsets, int n, int total){
    int i = blockIdx.x*1024 + threadIdx.x;
    if(i<n) offsets[i] += g_bsum[blockIdx.x];
    if(i==0) offsets[n] = total;
}
__global__ void fill_k(const int* __restrict__ key, const int* __restrict__ src,
                       int* __restrict__ cursor, int* __restrict__ idx, int n){
    int i = blockIdx.x*256 + threadIdx.x;
    if(i < n){
        int d = key[i];
        int p = atomicAdd(&cursor[d], 1);
        idx[p] = src ? src[i] : i;
    }
}
__global__ void segstart_k(const int* __restrict__ batch, int E){
    int b = threadIdx.x;
    if(b > NBD) return;
    int lo=0, hi=E;
    while(lo<hi){ int mid=(lo+hi)>>1; if(batch[mid] < b) lo=mid+1; else hi=mid; }
    g_segstart[b]=lo;
}

// ---------------- message passing (8 thr/edge, 8 feats/thread) -------------
// HP=0: prev is fp32 (ea). HP=1: prev is fp16 (out of previous iter).
template<int HP>
__global__ void msgpass_k(const void* __restrict__ prevv, __half* __restrict__ out,
                          const float* __restrict__ ea, const float* __restrict__ gatW,
                          float* __restrict__ xw, int E)
{
    int e = (blockIdx.x*256 + threadIdx.x) >> 3;
    int h = threadIdx.x & 7;
    if(e >= E) return;
    const float4* pe = (const float4*)(ea + (size_t)e*FD);
    float4 A0 = pe[2*h], A1 = pe[2*h+1];
    float a0=A0.x,a1=A0.y,a2=A0.z,a3=A0.w,a4=A1.x,a5=A1.y,a6=A1.z,a7=A1.w;
    int s = g_offsets[e], t = g_offsets[e+1];
    for(int k=s;k<t;k++){
        int i0 = g_idx[k];
        if(HP){
            uint4 u = ((const uint4*)((const __half*)prevv + (size_t)i0*FD))[h];
            float2 f0 = __half22float2(*(__half2*)&u.x);
            float2 f1 = __half22float2(*(__half2*)&u.y);
            float2 f2 = __half22float2(*(__half2*)&u.z);
            float2 f3 = __half22float2(*(__half2*)&u.w);
            a0+=f0.x; a1+=f0.y; a2+=f1.x; a3+=f1.y;
            a4+=f2.x; a5+=f2.y; a6+=f3.x; a7+=f3.y;
        } else {
            const float4* pr = (const float4*)((const float*)prevv + (size_t)i0*FD);
            float4 v0 = pr[2*h], v1 = pr[2*h+1];
            a0+=v0.x; a1+=v0.y; a2+=v0.z; a3+=v0.w;
            a4+=v1.x; a5+=v1.y; a6+=v1.z; a7+=v1.w;
        }
    }
    __half2 o0 = __floats2half2_rn(a0,a1);
    __half2 o1 = __floats2half2_rn(a2,a3);
    __half2 o2 = __floats2half2_rn(a4,a5);
    __half2 o3 = __floats2half2_rn(a6,a7);
    uint4 w;
    w.x = *(uint32_t*)&o0; w.y = *(uint32_t*)&o1;
    w.z = *(uint32_t*)&o2; w.w = *(uint32_t*)&o3;
    ((uint4*)(out + (size_t)e*FD))[h] = w;
    const float4* gw4 = (const float4*)gatW;
    float4 g0 = gw4[2*h], g1 = gw4[2*h+1];
    float d = a0*g0.x + a1*g0.y + a2*g0.z + a3*g0.w
            + a4*g1.x + a5*g1.y + a6*g1.z + a7*g1.w;
#pragma unroll
    for(int o=4;o;o>>=1) d += __shfl_xor_sync(0xffffffffu, d, o);
    if(h==0) xw[e] = d;
}

// ---------------- GAT edge softmax -> xc ----------------
__device__ __forceinline__ float leaky02(float v){ return v >= 0.f ? v : 0.2f*v; }
__global__ void xc_k(const float* __restrict__ asrc, const float* __restrict__ adst,
                     const float* __restrict__ gbias, const float* __restrict__ xw, int E)
{
    int e = blockIdx.x*256 + threadIdx.x;
    if(e >= E) return;
    float as_ = __ldg(asrc), ad_ = __ldg(adst);
    float xwe = xw[e];
    float adv = xwe * ad_;
    int s = g_offsets[e], t = g_offsets[e+1];
    float m = leaky02(xwe*as_ + adv);
    for(int k=s;k<t;k++){
        float v = leaky02(xw[g_idx[k]]*as_ + adv);
        m = fmaxf(m, v);
    }
    float sum = expf(leaky02(xwe*as_ + adv) - m);
    float num = sum * xwe;
    for(int k=s;k<t;k++){
        float xws = xw[g_idx[k]];
        float ee = expf(leaky02(xws*as_ + adv) - m);
        sum += ee; num = fmaf(ee, xws, num);
    }
    g_xc[e] = num/(sum + 1e-16f) + __ldg(gbias);
}

// ---------------- attention pool: phase 1 ----------------
__global__ void pool1_k()
{
    __shared__ float sh[256];
    int b = blockIdx.x, tid = threadIdx.x;
    int s = g_segstart[b], t = g_segstart[b+1];
    float m = -3.4e38f;
    for(int i=s+tid;i<t;i+=256) m = fmaxf(m, g_xc[i]);
    sh[tid]=m; __syncthreads();
    for(int o=128;o;o>>=1){ if(tid<o) sh[tid]=fmaxf(sh[tid],sh[tid+o]); __syncthreads(); }
    float mm = sh[0]; __syncthreads();
    float ss = 0.f;
    for(int i=s+tid;i<t;i+=256) ss += expf(g_xc[i]-mm);
    sh[tid]=ss; __syncthreads();
    for(int o=128;o;o>>=1){ if(tid<o) sh[tid]+=sh[tid+o]; __syncthreads(); }
    if(tid==0){ g_pm[b]=mm; g_pd[b]=sh[0]+1e-16f; }
    if(tid < 64) g_gout[b*FD+tid] = 0.f;
}

// ---------------- attention pool: phase 2 (8 blocks/batch, fp16 out) -------
__global__ void pool2_k(const __half* __restrict__ out_t)
{
    __shared__ float sh[256];
    int b = blockIdx.x >> 3, chunk = blockIdx.x & 7;
    int tid = threadIdx.x;
    int s = g_segstart[b], t = g_segstart[b+1];
    float mm = g_pm[b], inv = 1.f/g_pd[b];
    int c = tid & 63, grp = tid >> 6;
    float acc = 0.f;
    for(int i = s + chunk*4 + grp; i < t; i += 32){
        float w = expf(g_xc[i]-mm);
        acc = fmaf(__half2float(out_t[(size_t)i*FD + c]), w, acc);
    }
    sh[tid]=acc; __syncthreads();
    if(tid < 64){
        float v = (sh[tid]+sh[64+tid]+sh[128+tid]+sh[192+tid]) * inv;
        atomicAdd(&g_gout[b*FD+tid], v);
    }
}

// ---------------- gt = tanh(gout @ Wg + bg) ----------------
__global__ void gt_k(const float* __restrict__ Wg, const float* __restrict__ bg,
                     float* __restrict__ gt)
{
    __shared__ float sg[64];
    int b = blockIdx.x, f = threadIdx.x;
    sg[f] = g_gout[b*FD+f]; __syncthreads();
    float acc = 0.f;
#pragma unroll 8
    for(int c=0;c<64;c++) acc = fmaf(sg[c], Wg[c*64+f], acc);
    gt[b*FD+f] = tanhf(acc + bg[f]);
}

__global__ void scatt_k(const float* __restrict__ a, const float* __restrict__ abias)
{
    int b = blockIdx.x, lane = threadIdx.x;
    float l0=0.f,l1=0.f,l2=0.f;
    for(int f=lane; f<64; f+=32){
        float g0 = g_gt[0*NBD*FD + b*FD + f];
        float g1 = g_gt[1*NBD*FD + b*FD + f];
        float g2 = g_gt[2*NBD*FD + b*FD + f];
        l0 = fmaf(g0, a[f*3+0], l0);
        l1 = fmaf(g1, a[f*3+1], l1);
        l2 = fmaf(g2, a[f*3+2], l2);
    }
#pragma unroll
    for(int o=16;o;o>>=1){
        l0 += __shfl_xor_sync(0xffffffffu,l0,o);
        l1 += __shfl_xor_sync(0xffffffffu,l1,o);
        l2 += __shfl_xor_sync(0xffffffffu,l2,o);
    }
    if(lane==0){
        l0 += abias[0]; l1 += abias[1]; l2 += abias[2];
        float m = fmaxf(l0, fmaxf(l1,l2));
        float e0 = expf(l0-m), e1 = expf(l1-m), e2 = expf(l2-m);
        float inv = 1.f/(e0+e1+e2);
        g_scatt[b*3+0]=e0*inv; g_scatt[b*3+1]=e1*inv; g_scatt[b*3+2]=e2*inv;
    }
}

// ---------------- xn = x + gather(mixed fp16 out), fused lin1 stats --------
__global__ void xnmix_k(const float* __restrict__ x,
                        const __half* __restrict__ o0, const __half* __restrict__ o1,
                        const __half* __restrict__ o2, const int* __restrict__ batch,
                        float* __restrict__ xn, int N)
{
    __shared__ float ssm[FD], ssq[FD];
    int tid = threadIdx.x;
    if(tid < FD){ ssm[tid]=0.f; ssq[tid]=0.f; }
    __syncthreads();
    int n = (blockIdx.x*256 + tid) >> 3;
    int h = tid & 7;
    float a[8];
    if(n < N){
        const float4* px = (const float4*)(x + (size_t)n*FD);
        float4 X0 = px[2*h], X1 = px[2*h+1];
        a[0]=X0.x; a[1]=X0.y; a[2]=X0.z; a[3]=X0.w;
        a[4]=X1.x; a[5]=X1.y; a[6]=X1.z; a[7]=X1.w;
        int s = g_noffsets[n], t = g_noffsets[n+1];
        for(int k=s;k<t;k++){
            int e = g_nidx[k];
            int b = batch[e];
            float w0 = g_scatt[b*3], w1 = g_scatt[b*3+1], w2 = g_scatt[b*3+2];
            uint4 u0 = ((const uint4*)(o0 + (size_t)e*FD))[h];
            uint4 u1 = ((const uint4*)(o1 + (size_t)e*FD))[h];
            uint4 u2 = ((const uint4*)(o2 + (size_t)e*FD))[h];
            const uint32_t* p0 = &u0.x;
            const uint32_t* p1 = &u1.x;
            const uint32_t* p2 = &u2.x;
#pragma unroll
            for(int j=0;j<4;j++){
                float2 f0 = __half22float2(*(__half2*)&p0[j]);
                float2 f1 = __half22float2(*(__half2*)&p1[j]);
                float2 f2 = __half22float2(*(__half2*)&p2[j]);
                a[2*j  ] += f0.x*w0 + f1.x*w1 + f2.x*w2;
                a[2*j+1] += f0.y*w0 + f1.y*w1 + f2.y*w2;
            }
        }
        float4 W0, W1;
        W0.x=a[0]; W0.y=a[1]; W0.z=a[2]; W0.w=a[3];
        W1.x=a[4]; W1.y=a[5]; W1.z=a[6]; W1.w=a[7];
        float4* po = (float4*)(xn + (size_t)n*FD);
        po[2*h] = W0; po[2*h+1] = W1;
        int c0 = h*8;
#pragma unroll
        for(int j=0;j<8;j++){
            atomicAdd(&ssm[c0+j], a[j]);
            atomicAdd(&ssq[c0+j], a[j]*a[j]);
        }
    }
    __syncthreads();
    if(tid < FD){
        atomicAdd(&g_ssum5[tid], ssm[tid]);
        atomicAdd(&g_ssq5[tid],  ssq[tid]);
    }
}

// ---------------- host ----------------
extern "C" void kernel_launch(void* const* d_in, const int* in_sizes, int n_in,
                              void* d_out, int out_size)
{
    bool setupOrder = (in_sizes[2] > 100000);
    int IX, IEA, IEI, ILG, IBATCH, IWU, IWV, IWE, IGW, IAS, IAD, IGB, IA, IAB, IWG, IBG;
    int IB1G, IB1B, IW1, Ib1, IBNG, IBNB, IPR, IW, Ib, IB5G, IB5B, IPR5, IW5, Ib5;
    if(setupOrder){
        IX=0; IEA=1; IEI=2; ILG=3; IBATCH=4; IWU=5; IWV=6; IWE=7; IGW=8; IAS=9; IAD=10; IGB=11;
        IA=12; IAB=13; IWG=14; IBG=15; IB1G=16; IB1B=17; IW1=18; Ib1=19; IBNG=20; IBNB=21;
        IPR=22; IW=23; Ib=24; IB5G=25; IB5B=26; IPR5=27; IW5=28; Ib5=29;
    } else {
        IX=0; IEA=1; IWU=2; IWV=3; IWE=4; IGW=5; IAS=6; IAD=7; IGB=8; IA=9; IAB=10; IWG=11; IBG=12;
        IB1G=13; IB1B=14; IW1=15; Ib1=16; IBNG=17; IBNB=18; IPR=19; IW=20; Ib=21;
        IB5G=22; IB5B=23; IPR5=24; IW5=25; Ib5=26; IEI=27; ILG=28; IBATCH=29;
    }
    const float* x     = (const float*)d_in[IX];
    const float* eattr = (const float*)d_in[IEA];
    const int*   ei    = (const int*)d_in[IEI];
    const int*   lg    = (const int*)d_in[ILG];
    const int*   batch = (const int*)d_in[IBATCH];
    const float* W_u = (const float*)d_in[IWU];
    const float* W_v = (const float*)d_in[IWV];
    const float* W_e = (const float*)d_in[IWE];
    const float* gatW = (const float*)d_in[IGW];
    const float* asrc = (const float*)d_in[IAS];
    const float* adst = (const float*)d_in[IAD];
    const float* gbias = (const float*)d_in[IGB];
    const float* a_att = (const float*)d_in[IA];
    const float* a_bias = (const float*)d_in[IAB];
    const float* W_gout = (const float*)d_in[IWG];
    const float* b_gout = (const float*)d_in[IBG];
    const float* bn1g = (const float*)d_in[IB1G];
    const float* bn1b = (const float*)d_in[IB1B];
    const float* W1 = (const float*)d_in[IW1];
    const float* b1 = (const float*)d_in[Ib1];
    const float* bng = (const float*)d_in[IBNG];
    const float* bnb = (const float*)d_in[IBNB];
    const float* pr  = (const float*)d_in[IPR];
    const float* Wm  = (const float*)d_in[IW];
    const float* bm  = (const float*)d_in[Ib];
    const float* bn5g = (const float*)d_in[IB5G];
    const float* bn5b = (const float*)d_in[IB5B];
    const float* pr5 = (const float*)d_in[IPR5];
    const float* W5 = (const float*)d_in[IW5];
    const float* b5 = (const float*)d_in[Ib5];

    const int N  = in_sizes[IX] / FD;
    const int E  = in_sizes[IEA] / 16;
    const int LE = in_sizes[ILG] / 2;
    const int* ei0 = ei;       const int* ei1 = ei + E;
    const int* lg0 = lg;       const int* lg1 = lg + LE;

    void *p;
    float *xuv_p, *ea_p, *xn_p, *bufA, *bufB, *bufC, *gt_p, *xw_p;
    float *ssum5_p, *ssq5_p;
    __half *outh_p;
    int *counts_p, *offsets_p, *cursor_p, *ncounts_p, *noffsets_p, *ncursor_p, *nidx_p, *idx_p;
    uint32_t *w1t, *wmt, *w5t;
    cudaGetSymbolAddress(&p, g_xuv);    xuv_p=(float*)p;
    cudaGetSymbolAddress(&p, g_ea);     ea_p=(float*)p;
    cudaGetSymbolAddress(&p, g_outh);   outh_p=(__half*)p;
    cudaGetSymbolAddress(&p, g_xn);     xn_p=(float*)p;
    cudaGetSymbolAddress(&p, g_bufA);   bufA=(float*)p;
    cudaGetSymbolAddress(&p, g_bufB);   bufB=(float*)p;
    cudaGetSymbolAddress(&p, g_bufC);   bufC=(float*)p;
    cudaGetSymbolAddress(&p, g_gt);     gt_p=(float*)p;
    cudaGetSymbolAddress(&p, g_xw);     xw_p=(float*)p;
    cudaGetSymbolAddress(&p, g_ssum5);  ssum5_p=(float*)p;
    cudaGetSymbolAddress(&p, g_ssq5);   ssq5_p=(float*)p;
    cudaGetSymbolAddress(&p, g_counts); counts_p=(int*)p;
    cudaGetSymbolAddress(&p, g_offsets);offsets_p=(int*)p;
    cudaGetSymbolAddress(&p, g_cursor); cursor_p=(int*)p;
    cudaGetSymbolAddress(&p, g_ncounts); ncounts_p=(int*)p;
    cudaGetSymbolAddress(&p, g_noffsets);noffsets_p=(int*)p;
    cudaGetSymbolAddress(&p, g_ncursor); ncursor_p=(int*)p;
    cudaGetSymbolAddress(&p, g_nidx);    nidx_p=(int*)p;
    cudaGetSymbolAddress(&p, g_idx);     idx_p=(int*)p;
    cudaGetSymbolAddress(&p, g_W1t);    w1t=(uint32_t*)p;
    cudaGetSymbolAddress(&p, g_Wmt);    wmt=(uint32_t*)p;
    cudaGetSymbolAddress(&p, g_W5t);    w5t=(uint32_t*)p;

    static cudaStream_t s1 = nullptr;
    static cudaEvent_t ev0=nullptr, evCSR=nullptr, evNCSR=nullptr,
                       evM[NITD]={nullptr,nullptr,nullptr}, evScatt=nullptr, evCvt=nullptr;
    if(!s1){
        cudaStreamCreateWithFlags(&s1, cudaStreamNonBlocking);
        cudaEventCreateWithFlags(&ev0,    cudaEventDisableTiming);
        cudaEventCreateWithFlags(&evCSR,  cudaEventDisableTiming);
        cudaEventCreateWithFlags(&evNCSR, cudaEventDisableTiming);
        for(int t=0;t<NITD;t++) cudaEventCreateWithFlags(&evM[t], cudaEventDisableTiming);
        cudaEventCreateWithFlags(&evScatt,cudaEventDisableTiming);
        cudaEventCreateWithFlags(&evCvt,  cudaEventDisableTiming);
    }
    cudaStream_t s0 = 0;

    // ---- fork ----
    cudaEventRecord(ev0, s0);
    cudaStreamWaitEvent(s1, ev0, 0);

    // ===== s1: stats zero, weight conversion, line CSR, node CSR =====
    zero_stats5_k<<<cdiv(5*SFD,256),256,0,s1>>>();
    cvtW_k<<<cdiv(FD*SFD,256),256,0,s1>>>(W1, w1t, FD, SFD, SFD);
    cvtW_k<<<cdiv(3*SFD*SFD,256),256,0,s1>>>(Wm, wmt, 3*SFD, SFD, SFD);
    cvtW_k<<<cdiv(SFD*128,256),256,0,s1>>>(W5, w5t, SFD, FD, 128);
    cudaEventRecord(evCvt, s1);
    cudaMemsetAsync(counts_p, 0, (size_t)E*sizeof(int), s1);
    hist_k<<<cdiv(LE,256),256,0,s1>>>(lg1, counts_p, LE);
    int nblkE = cdiv(E,1024);
    scan1_k<<<nblkE,1024,0,s1>>>(counts_p, offsets_p, E);
    scan2_k<<<1,512,0,s1>>>(nblkE);
    scan3_k<<<nblkE,1024,0,s1>>>(offsets_p, E, LE);
    cudaMemcpyAsync(cursor_p, offsets_p, (size_t)E*sizeof(int), cudaMemcpyDeviceToDevice, s1);
    fill_k<<<cdiv(LE,256),256,0,s1>>>(lg1, lg0, cursor_p, idx_p, LE);
    segstart_k<<<1,NBD+1,0,s1>>>(batch, E);
    cudaEventRecord(evCSR, s1);
    cudaMemsetAsync(ncounts_p, 0, (size_t)N*sizeof(int), s1);
    hist_k<<<cdiv(E,256),256,0,s1>>>(ei1, ncounts_p, E);
    int nblkN = cdiv(N,1024);
    scan1_k<<<nblkN,1024,0,s1>>>(ncounts_p, noffsets_p, N);
    scan2_k<<<1,512,0,s1>>>(nblkN);
    scan3_k<<<nblkN,1024,0,s1>>>(noffsets_p, N, E);
    cudaMemcpyAsync(ncursor_p, noffsets_p, (size_t)N*sizeof(int), cudaMemcpyDeviceToDevice, s1);
    fill_k<<<cdiv(E,256),256,0,s1>>>(ei1, nullptr, ncursor_p, nidx_p, E);
    cudaEventRecord(evNCSR, s1);

    // ===== s0: xuv -> ea =====
    gemm_xuv_k<<<dim3(cdiv(N,128),2),256,0,s0>>>(x, W_u, W_v, xuv_p, N);
    ea_kernel<<<cdiv(E,32),256,0,s0>>>(xuv_p, eattr, W_e, ei0, ei1, ea_p, E);

    // ===== iterations =====
    cudaStreamWaitEvent(s0, evCSR, 0);
    const size_t OSTRIDE = (size_t)MAXE*FD;
    for(int t=0;t<NITD;t++){
        __half* outt = outh_p + (size_t)t*OSTRIDE;
        float* xwt  = xw_p + (size_t)t*MAXE;
        if(t==0)
            msgpass_k<0><<<cdiv(E,32),256,0,s0>>>(ea_p, outt, ea_p, gatW, xwt, E);
        else
            msgpass_k<1><<<cdiv(E,32),256,0,s0>>>(outh_p + (size_t)(t-1)*OSTRIDE, outt,
                                                  ea_p, gatW, xwt, E);
        cudaEventRecord(evM[t], s0);
        cudaStreamWaitEvent(s1, evM[t], 0);
        xc_k<<<cdiv(E,256),256,0,s1>>>(asrc, adst, gbias, xwt, E);
        pool1_k<<<NBD,256,0,s1>>>();
        pool2_k<<<NBD*8,256,0,s1>>>(outt);
        gt_k<<<NBD,64,0,s1>>>(W_gout, b_gout, gt_p + (size_t)t*NBD*FD);
    }
    scatt_k<<<NBD,32,0,s1>>>(a_att, a_bias);
    cudaEventRecord(evScatt, s1);

    // ===== s0: xn (fused lin1 stats -> slot 0) -> LinearBlock =====
    cudaStreamWaitEvent(s0, evScatt, 0);
    cudaStreamWaitEvent(s0, evNCSR, 0);
    xnmix_k<<<cdiv(N,32),256,0,s0>>>(x, outh_p, outh_p+OSTRIDE, outh_p+2*OSTRIDE,
                                     batch, xn_p, N);

    cudaStreamWaitEvent(s0, evCvt, 0);
    gemm_tc<1,1><<<dim3(cdiv(N,128),SFD/128),256,0,s0>>>(xn_p, w1t, bufA, N, FD, SFD, SFD,
        ssum5_p, ssq5_p, bn1g, bn1b, N, ssum5_p+SFD, ssq5_p+SFD, nullptr, b1, nullptr);
    gemm_tc<2,1><<<dim3(cdiv(N,128),SFD/128),256,0,s0>>>(bufA, wmt, bufB, N, SFD, SFD, SFD,
        ssum5_p+SFD, ssq5_p+SFD, bng, bnb, N, ssum5_p+2*SFD, ssq5_p+2*SFD, pr, bm, nullptr);
    gemm_tc<2,1><<<dim3(cdiv(N,128),SFD/128),256,0,s0>>>(bufB, wmt+(size_t)SFD*SFD, bufC, N, SFD, SFD, SFD,
        ssum5_p+2*SFD, ssq5_p+2*SFD, bng+SFD, bnb+SFD, N, ssum5_p+3*SFD, ssq5_p+3*SFD, pr+1, bm+SFD, bufA);
    gemm_tc<2,1><<<dim3(cdiv(N,128),SFD/128),256,0,s0>>>(bufC, wmt+(size_t)2*SFD*SFD, bufA, N, SFD, SFD, SFD,
        ssum5_p+3*SFD, ssq5_p+3*SFD, bng+2*SFD, bnb+2*SFD, N, ssum5_p+4*SFD, ssq5_p+4*SFD, pr+2, bm+2*SFD, bufC);
    gemm_tc<2,0><<<dim3(cdiv(N,128),1),256,0,s0>>>(bufA, w5t, (float*)d_out, N, SFD, FD, 128,
        ssum5_p+4*SFD, ssq5_p+4*SFD, bn5g, bn5b, N, nullptr, nullptr, pr5, b5, nullptr);
}

// round 17
// speedup vs baseline: 1.1120x; 1.0785x over previous
#include <cuda_runtime.h>
#include <cuda_fp16.h>
#include <stdint.h>
#include <math.h>

#define FD   64
#define SFD  384
#define NITD 3
#define NBD  256
#define MAXN 50000
#define MAXE 400000
#define MAXLE 1600000

static inline int cdiv(int a, int b){ return (a + b - 1) / b; }

// ---------------- scratch ----------------
__device__ float  g_xuv[(size_t)MAXN*128];
__device__ float  g_ea[(size_t)MAXE*FD];
__device__ __half g_outh[NITD][(size_t)MAXE*FD];
__device__ int   g_counts[MAXE];
__device__ int   g_offsets[MAXE+1];
__device__ int   g_cursor[MAXE];
__device__ int   g_ncounts[MAXN];
__device__ int   g_noffsets[MAXN+1];
__device__ int   g_ncursor[MAXN];
__device__ int   g_nidx[MAXE];
__device__ int   g_bsum[1024];
__device__ int   g_idx[MAXLE];
__device__ float g_xw[NITD][MAXE];
__device__ float g_xc[MAXE];
__device__ int   g_segstart[NBD+1];
__device__ float g_pm[NBD];
__device__ float g_pd[NBD];
__device__ float g_gout[NBD*FD];
__device__ float g_gt[NITD*NBD*FD];
__device__ float g_scatt[NBD*NITD];
__device__ float g_xn[(size_t)MAXN*FD];
__device__ float g_bufA[(size_t)MAXN*SFD];
__device__ float g_bufB[(size_t)MAXN*SFD];
__device__ float g_bufC[(size_t)MAXN*SFD];
__device__ float g_ssum5[5*SFD];
__device__ float g_ssq5[5*SFD];
// fp16 TRANSPOSED weights: Wt[n][k]
__device__ __half g_W1t[SFD*FD];        // [384 n][64 k]
__device__ __half g_Wmt[3*SFD*SFD];     // 3 x [384 n][384 k]
__device__ __half g_W5t[128*SFD];       // [128 n][384 k] (n>=64 zero)

// ---------------- mma helpers ----------------
__device__ __forceinline__ void mma_f16(float (&c)[4],
    uint32_t a0, uint32_t a1, uint32_t a2, uint32_t a3, uint32_t b0, uint32_t b1)
{
    asm volatile("mma.sync.aligned.m16n8k16.row.col.f32.f16.f16.f32 "
        "{%0,%1,%2,%3}, {%4,%5,%6,%7}, {%8,%9}, {%0,%1,%2,%3};"
        : "+f"(c[0]), "+f"(c[1]), "+f"(c[2]), "+f"(c[3])
        : "r"(a0), "r"(a1), "r"(a2), "r"(a3), "r"(b0), "r"(b1));
}
__device__ __forceinline__ uint32_t smem_u32(const void* p){
    return (uint32_t)__cvta_generic_to_shared(p);
}

// ---------------- weight convert: fp32 [K][N] -> fp16 transposed [ldn][K] --
__global__ void cvtWh_k(const float* __restrict__ src, __half* __restrict__ dst,
                        int K, int N, int ldn)
{
    int i = blockIdx.x*256 + threadIdx.x;
    if(i >= ldn*K) return;
    int n = i / K, k = i % K;
    dst[i] = (n < N) ? __float2half(src[(size_t)k*N + n]) : __float2half(0.f);
}
__global__ void zero_stats5_k(){
    int i = blockIdx.x*256 + threadIdx.x;
    if(i < 5*SFD){ g_ssum5[i]=0.f; g_ssq5[i]=0.f; }
}

// ============================================================================
// fp16 tensor-core GEMM — R10/R16 pipeline structure (BK=16, 2-buffer,
// 2 syncs/iter), m16n8k16 fragments. BN affine in-prologue (fp32), fp32
// accumulate, fp32 A/C buffers. B = transposed fp16 weights [n][k], ldk.
// As[r][kpair] stride 12 (bank 12g+q injective); Bs[n][kpair] stride 12.
// ============================================================================
template<int TRANS, int STATS>
__global__ __launch_bounds__(256)
void gemm_tc(const float* __restrict__ A, const __half* __restrict__ B,
             float* __restrict__ C, int M, int K, int N, int ldk,
             const float* __restrict__ ssum, const float* __restrict__ ssq,
             const float* __restrict__ gamma, const float* __restrict__ gbeta,
             int Mstat,
             float* __restrict__ sumo, float* __restrict__ ssqo,
             const float* __restrict__ prw, const float* __restrict__ bias,
             const float* __restrict__ res)
{
    const int BM=128, BN=128, BK=16;
    const int SA=12, SB=12;                 // uints (half2) per row
    __shared__ uint32_t As[2][BM*SA];
    __shared__ uint32_t Bs[2][BN*SB];
    __shared__ float scol[BN], sqcol[BN];
    __shared__ float salpha[SFD], sbeta[SFD];

    int tid  = threadIdx.x;
    int wid  = tid >> 5, lane = tid & 31;
    int q    = lane & 3, g = lane >> 2;
    int wm   = (wid >> 2) * 64;
    int wn   = (wid & 3) * 32;
    int row0 = blockIdx.x * BM;
    int col0 = blockIdx.y * BN;
    float pw = (TRANS==2) ? __ldg(prw) : 0.f;

    float invM = 1.f / (float)Mstat;
    for(int k = tid; k < K; k += 256){
        float m = ssum[k]*invM;
        float v = ssq[k]*invM - m*m;
        float al = gamma[k]*rsqrtf(v + 1e-5f);
        salpha[k] = al;
        sbeta[k]  = gbeta[k] - m*al;
    }
    if(STATS && tid < BN){ scol[tid]=0.f; sqcol[tid]=0.f; }

    float acc[4][4][4];
#pragma unroll
    for(int mi=0;mi<4;mi++)
#pragma unroll
        for(int ni=0;ni<4;ni++)
#pragma unroll
            for(int j=0;j<4;j++) acc[mi][ni][j]=0.f;

    float4 ra[2];
    int ar[2], ac[2];
#pragma unroll
    for(int i=0;i<2;i++){
        int idx = tid + i*256;
        ar[i] = idx >> 2;  ac[i] = (idx & 3) << 2;   // A: 128 rows x 16 k (4 floats/thread x2)
    }
    int bnn = tid >> 1, bch = tid & 1;               // B: 128 n x 2 halves-of-row

    auto ldA = [&](int k0){
#pragma unroll
        for(int i=0;i<2;i++){
            int grow = row0 + ar[i];
            ra[i] = (grow < M) ? *(const float4*)(A + (size_t)grow*K + k0 + ac[i])
                               : make_float4(0.f,0.f,0.f,0.f);
        }
    };
    auto cpB = [&](int buf, int k0){
        const __half* src = B + (size_t)(col0 + bnn)*ldk + k0 + bch*8;
        uint32_t daddr = smem_u32(&Bs[buf][bnn*SB + bch*4]);
        asm volatile("cp.async.ca.shared.global [%0], [%1], 16;\n"
                     :: "r"(daddr), "l"(src));
        asm volatile("cp.async.commit_group;\n");
    };
    auto stA = [&](int buf, int k0){
#pragma unroll
        for(int i=0;i<2;i++){
            float v[4] = {ra[i].x, ra[i].y, ra[i].z, ra[i].w};
#pragma unroll
            for(int j=0;j<4;j++){
                int gk = k0 + ac[i] + j;
                float vv = fmaf(salpha[gk], v[j], sbeta[gk]);
                if(TRANS==2) vv = vv >= 0.f ? vv : pw*vv;
                v[j] = vv;
            }
            __half2 h0 = __floats2half2_rn(v[0], v[1]);
            __half2 h1 = __floats2half2_rn(v[2], v[3]);
            uint2 o;
            o.x = *(uint32_t*)&h0; o.y = *(uint32_t*)&h1;
            *(uint2*)&As[buf][ar[i]*SA + (ac[i]>>1)] = o;
        }
    };

    ldA(0);
    cpB(0, 0);
    __syncthreads();   // salpha/sbeta visible before first stA

    int nIter = K / BK;
    for(int it=0; it<nIter; it++){
        int buf = it & 1;
        stA(buf, it*BK);
        if(it+1 < nIter) ldA((it+1)*BK);
        asm volatile("cp.async.wait_group 0;\n");
        __syncthreads();
        if(it+1 < nIter) cpB(buf^1, (it+1)*BK);
        const uint32_t* as = As[buf];
        const uint32_t* bs = Bs[buf];
        uint32_t af[4][4];
#pragma unroll
        for(int mi=0;mi<4;mi++){
            int base = wm + mi*16 + g;
            af[mi][0] = as[ base   *SA + q    ];   // A[g][2q..]
            af[mi][1] = as[(base+8)*SA + q    ];   // A[g+8][2q..]
            af[mi][2] = as[ base   *SA + q + 4];   // A[g][2q+8..]
            af[mi][3] = as[(base+8)*SA + q + 4];   // A[g+8][2q+8..]
        }
        uint32_t bf[4][2];
#pragma unroll
        for(int ni=0;ni<4;ni++){
            int n = wn + ni*8 + g;
            bf[ni][0] = bs[n*SB + q    ];          // B[2q..][n]
            bf[ni][1] = bs[n*SB + q + 4];          // B[2q+8..][n]
        }
#pragma unroll
        for(int mi=0;mi<4;mi++)
#pragma unroll
            for(int ni=0;ni<4;ni++)
                mma_f16(acc[mi][ni], af[mi][0], af[mi][1], af[mi][2], af[mi][3],
                        bf[ni][0], bf[ni][1]);
        __syncthreads();
    }

    // ---- epilogue (identical to R16) ----
#pragma unroll
    for(int ni=0; ni<4; ni++){
        int cg = col0 + wn + ni*8 + 2*q;
        if(cg >= N) continue;
        float b0v = bias ? bias[cg]   : 0.f;
        float b1v = bias ? bias[cg+1] : 0.f;
        float s0=0.f,s1=0.f,q0=0.f,q1=0.f;
#pragma unroll
        for(int mi=0; mi<4; mi++){
            int r0 = row0 + wm + mi*16 + g;
#pragma unroll
            for(int h=0; h<2; h++){
                int r = r0 + h*8;
                if(r >= M) continue;
                float v0 = acc[mi][ni][h*2+0] + b0v;
                float v1 = acc[mi][ni][h*2+1] + b1v;
                if(res){
                    float2 rr = *(const float2*)(res + (size_t)r*N + cg);
                    v0 = (v0 + rr.x)*0.5f;
                    v1 = (v1 + rr.y)*0.5f;
                }
                float2 w; w.x=v0; w.y=v1;
                *(float2*)(C + (size_t)r*N + cg) = w;
                if(STATS){
                    s0 += v0; s1 += v1;
                    q0 = fmaf(v0,v0,q0); q1 = fmaf(v1,v1,q1);
                }
            }
        }
        if(STATS){
            int lc = wn + ni*8 + 2*q;
            atomicAdd(&scol[lc],   s0); atomicAdd(&sqcol[lc],   q0);
            atomicAdd(&scol[lc+1], s1); atomicAdd(&sqcol[lc+1], q1);
        }
    }
    if(STATS){
        __syncthreads();
        if(tid < BN && col0 + tid < N){
            atomicAdd(&sumo[col0+tid], scol[tid]);
            atomicAdd(&ssqo[col0+tid], sqcol[tid]);
        }
    }
}

// ---------------- fp32 GEMM for xuv ----------------
__global__ __launch_bounds__(256)
void gemm_xuv_k(const float* __restrict__ A, const float* __restrict__ Wu,
                const float* __restrict__ Wv, float* __restrict__ C, int M)
{
    const int BM=128, BN=64, BK=16, K=64, LDC=128;
    const float* B = (blockIdx.y == 0) ? Wu : Wv;
    __shared__ float As[BK][BM];
    __shared__ float Bs[BK][BN];
    int tid = threadIdx.x;
    int tx = tid & 15;
    int ty = tid >> 4;
    int row0 = blockIdx.x * BM;
    int cout0 = blockIdx.y * BN;
    float acc[8][4];
#pragma unroll
    for(int i=0;i<8;i++)
#pragma unroll
        for(int j=0;j<4;j++) acc[i][j]=0.f;

    for(int k0=0;k0<K;k0+=BK){
#pragma unroll
        for(int l=tid; l<512; l+=256){
            int r  = l >> 2;
            int c4 = (l & 3) << 2;
            int grow = row0 + r;
            float4 v = make_float4(0.f,0.f,0.f,0.f);
            if(grow < M) v = *(const float4*)(A + (size_t)grow*K + k0 + c4);
            As[c4  ][r]=v.x; As[c4+1][r]=v.y; As[c4+2][r]=v.z; As[c4+3][r]=v.w;
        }
        {
            int r  = tid >> 4;
            int c4 = (tid & 15) << 2;
            float4 v = *(const float4*)(B + (size_t)(k0+r)*64 + c4);
            *(float4*)(&Bs[r][c4]) = v;
        }
        __syncthreads();
#pragma unroll
        for(int k=0;k<BK;k++){
            float4 a0 = *(const float4*)(&As[k][ty*8]);
            float4 a1 = *(const float4*)(&As[k][ty*8+4]);
            float4 b0 = *(const float4*)(&Bs[k][tx*4]);
            float am[8] = {a0.x,a0.y,a0.z,a0.w,a1.x,a1.y,a1.z,a1.w};
            float bn[4] = {b0.x,b0.y,b0.z,b0.w};
#pragma unroll
            for(int i=0;i<8;i++)
#pragma unroll
                for(int j=0;j<4;j++) acc[i][j]=fmaf(am[i],bn[j],acc[i][j]);
        }
        __syncthreads();
    }
    int cbase = cout0 + tx*4;
#pragma unroll
    for(int i=0;i<8;i++){
        int r = row0 + ty*8 + i;
        if(r >= M) break;
        float4 v;
        v.x = acc[i][0]; v.y = acc[i][1]; v.z = acc[i][2]; v.w = acc[i][3];
        *(float4*)(C + (size_t)r*LDC + cbase) = v;
    }
}

// ---------------- ea (8 threads/edge, float4) ----------------
__global__ void ea_kernel(const float* __restrict__ xuv,
                          const float* __restrict__ eattr, const float* __restrict__ We,
                          const int* __restrict__ ei0, const int* __restrict__ ei1,
                          float* __restrict__ ea, int E)
{
    __shared__ float4 sW[16*16];
    for(int i=threadIdx.x;i<256;i+=256) sW[i] = ((const float4*)We)[i];
    __syncthreads();
    int e = (blockIdx.x*256 + threadIdx.x) >> 3;
    int h = threadIdx.x & 7;
    if(e >= E) return;
    int u = ei0[e], v = ei1[e];
    const float4* xv4 = (const float4*)xuv;
    float4 a0 = xv4[(size_t)u*32 + h];
    float4 a1 = xv4[(size_t)u*32 + 8 + h];
    float4 b0 = xv4[(size_t)v*32 + 16 + h];
    float4 b1 = xv4[(size_t)v*32 + 24 + h];
    float4 acc0, acc1;
    acc0.x=a0.x+b0.x; acc0.y=a0.y+b0.y; acc0.z=a0.z+b0.z; acc0.w=a0.w+b0.w;
    acc1.x=a1.x+b1.x; acc1.y=a1.y+b1.y; acc1.z=a1.z+b1.z; acc1.w=a1.w+b1.w;
    float w0 = eattr[(size_t)e*16 + h];
    float w1 = eattr[(size_t)e*16 + 8 + h];
    int lanebase = (threadIdx.x & 31) & ~7;
#pragma unroll
    for(int j=0;j<16;j++){
        float wj = __shfl_sync(0xffffffffu, (j<8)? w0 : w1, lanebase + (j & 7));
        float4 r0 = sW[j*16 + h];
        float4 r1 = sW[j*16 + 8 + h];
        acc0.x = fmaf(wj, r0.x, acc0.x); acc0.y = fmaf(wj, r0.y, acc0.y);
        acc0.z = fmaf(wj, r0.z, acc0.z); acc0.w = fmaf(wj, r0.w, acc0.w);
        acc1.x = fmaf(wj, r1.x, acc1.x); acc1.y = fmaf(wj, r1.y, acc1.y);
        acc1.z = fmaf(wj, r1.z, acc1.z); acc1.w = fmaf(wj, r1.w, acc1.w);
    }
    const float th = 1.f/3.f;
    acc0.x*=th; acc0.y*=th; acc0.z*=th; acc0.w*=th;
    acc1.x*=th; acc1.y*=th; acc1.z*=th; acc1.w*=th;
    float4* po = (float4*)(ea + (size_t)e*FD);
    po[h] = acc0; po[8+h] = acc1;
}

// ---------------- generic CSR build ----------------
__global__ void hist_k(const int* __restrict__ key, int* __restrict__ counts, int n){
    int i = blockIdx.x*256 + threadIdx.x;
    if(i < n) atomicAdd(&counts[key[i]], 1);
}
__global__ void scan1_k(const int* __restrict__ counts, int* __restrict__ offsets, int n){
    __shared__ int sh[1024];
    int tid = threadIdx.x;
    int i = blockIdx.x*1024 + tid;
    int v = (i<n) ? counts[i] : 0;
    sh[tid]=v; __syncthreads();
    for(int off=1; off<1024; off<<=1){
        int t = (tid>=off) ? sh[tid-off] : 0;
        __syncthreads();
        if(tid>=off) sh[tid]+=t;
        __syncthreads();
    }
    if(i<n) offsets[i] = sh[tid]-v;
    if(tid==1023) g_bsum[blockIdx.x]=sh[1023];
}
__global__ void scan2_k(int nb){
    __shared__ int sh[512];
    int tid = threadIdx.x;
    int v = (tid<nb)? g_bsum[tid] : 0;
    sh[tid]=v; __syncthreads();
    for(int off=1; off<512; off<<=1){
        int t = (tid>=off) ? sh[tid-off] : 0;
        __syncthreads();
        if(tid>=off) sh[tid]+=t;
        __syncthreads();
    }
    if(tid<nb) g_bsum[tid] = sh[tid]-v;
}
__global__ void scan3_k(int* __restrict__ offsets, int n, int total){
    int i = blockIdx.x*1024 + threadIdx.x;
    if(i<n) offsets[i] += g_bsum[blockIdx.x];
    if(i==0) offsets[n] = total;
}
__global__ void fill_k(const int* __restrict__ key, const int* __restrict__ src,
                       int* __restrict__ cursor, int* __restrict__ idx, int n){
    int i = blockIdx.x*256 + threadIdx.x;
    if(i < n){
        int d = key[i];
        int p = atomicAdd(&cursor[d], 1);
        idx[p] = src ? src[i] : i;
    }
}
__global__ void segstart_k(const int* __restrict__ batch, int E){
    int b = threadIdx.x;
    if(b > NBD) return;
    int lo=0, hi=E;
    while(lo<hi){ int mid=(lo+hi)>>1; if(batch[mid] < b) lo=mid+1; else hi=mid; }
    g_segstart[b]=lo;
}

// ---------------- message passing (8 thr/edge, 8 feats/thread) -------------
template<int HP>
__global__ void msgpass_k(const void* __restrict__ prevv, __half* __restrict__ out,
                          const float* __restrict__ ea, const float* __restrict__ gatW,
                          float* __restrict__ xw, int E)
{
    int e = (blockIdx.x*256 + threadIdx.x) >> 3;
    int h = threadIdx.x & 7;
    if(e >= E) return;
    const float4* pe = (const float4*)(ea + (size_t)e*FD);
    float4 A0 = pe[2*h], A1 = pe[2*h+1];
    float a0=A0.x,a1=A0.y,a2=A0.z,a3=A0.w,a4=A1.x,a5=A1.y,a6=A1.z,a7=A1.w;
    int s = g_offsets[e], t = g_offsets[e+1];
    for(int k=s;k<t;k++){
        int i0 = g_idx[k];
        if(HP){
            uint4 u = ((const uint4*)((const __half*)prevv + (size_t)i0*FD))[h];
            float2 f0 = __half22float2(*(__half2*)&u.x);
            float2 f1 = __half22float2(*(__half2*)&u.y);
            float2 f2 = __half22float2(*(__half2*)&u.z);
            float2 f3 = __half22float2(*(__half2*)&u.w);
            a0+=f0.x; a1+=f0.y; a2+=f1.x; a3+=f1.y;
            a4+=f2.x; a5+=f2.y; a6+=f3.x; a7+=f3.y;
        } else {
            const float4* pr = (const float4*)((const float*)prevv + (size_t)i0*FD);
            float4 v0 = pr[2*h], v1 = pr[2*h+1];
            a0+=v0.x; a1+=v0.y; a2+=v0.z; a3+=v0.w;
            a4+=v1.x; a5+=v1.y; a6+=v1.z; a7+=v1.w;
        }
    }
    __half2 o0 = __floats2half2_rn(a0,a1);
    __half2 o1 = __floats2half2_rn(a2,a3);
    __half2 o2 = __floats2half2_rn(a4,a5);
    __half2 o3 = __floats2half2_rn(a6,a7);
    uint4 w;
    w.x = *(uint32_t*)&o0; w.y = *(uint32_t*)&o1;
    w.z = *(uint32_t*)&o2; w.w = *(uint32_t*)&o3;
    ((uint4*)(out + (size_t)e*FD))[h] = w;
    const float4* gw4 = (const float4*)gatW;
    float4 g0 = gw4[2*h], g1 = gw4[2*h+1];
    float d = a0*g0.x + a1*g0.y + a2*g0.z + a3*g0.w
            + a4*g1.x + a5*g1.y + a6*g1.z + a7*g1.w;
#pragma unroll
    for(int o=4;o;o>>=1) d += __shfl_xor_sync(0xffffffffu, d, o);
    if(h==0) xw[e] = d;
}

// ---------------- GAT edge softmax -> xc ----------------
__device__ __forceinline__ float leaky02(float v){ return v >= 0.f ? v : 0.2f*v; }
__global__ void xc_k(const float* __restrict__ asrc, const float* __restrict__ adst,
                     const float* __restrict__ gbias, const float* __restrict__ xw, int E)
{
    int e = blockIdx.x*256 + threadIdx.x;
    if(e >= E) return;
    float as_ = __ldg(asrc), ad_ = __ldg(adst);
    float xwe = xw[e];
    float adv = xwe * ad_;
    int s = g_offsets[e], t = g_offsets[e+1];
    float m = leaky02(xwe*as_ + adv);
    for(int k=s;k<t;k++){
        float v = leaky02(xw[g_idx[k]]*as_ + adv);
        m = fmaxf(m, v);
    }
    float sum = expf(leaky02(xwe*as_ + adv) - m);
    float num = sum * xwe;
    for(int k=s;k<t;k++){
        float xws = xw[g_idx[k]];
        float ee = expf(leaky02(xws*as_ + adv) - m);
        sum += ee; num = fmaf(ee, xws, num);
    }
    g_xc[e] = num/(sum + 1e-16f) + __ldg(gbias);
}

// ---------------- attention pool: phase 1 ----------------
__global__ void pool1_k()
{
    __shared__ float sh[256];
    int b = blockIdx.x, tid = threadIdx.x;
    int s = g_segstart[b], t = g_segstart[b+1];
    float m = -3.4e38f;
    for(int i=s+tid;i<t;i+=256) m = fmaxf(m, g_xc[i]);
    sh[tid]=m; __syncthreads();
    for(int o=128;o;o>>=1){ if(tid<o) sh[tid]=fmaxf(sh[tid],sh[tid+o]); __syncthreads(); }
    float mm = sh[0]; __syncthreads();
    float ss = 0.f;
    for(int i=s+tid;i<t;i+=256) ss += expf(g_xc[i]-mm);
    sh[tid]=ss; __syncthreads();
    for(int o=128;o;o>>=1){ if(tid<o) sh[tid]+=sh[tid+o]; __syncthreads(); }
    if(tid==0){ g_pm[b]=mm; g_pd[b]=sh[0]+1e-16f; }
    if(tid < 64) g_gout[b*FD+tid] = 0.f;
}

// ---------------- attention pool: phase 2 (8 blocks/batch, fp16 out) -------
__global__ void pool2_k(const __half* __restrict__ out_t)
{
    __shared__ float sh[256];
    int b = blockIdx.x >> 3, chunk = blockIdx.x & 7;
    int tid = threadIdx.x;
    int s = g_segstart[b], t = g_segstart[b+1];
    float mm = g_pm[b], inv = 1.f/g_pd[b];
    int c = tid & 63, grp = tid >> 6;
    float acc = 0.f;
    for(int i = s + chunk*4 + grp; i < t; i += 32){
        float w = expf(g_xc[i]-mm);
        acc = fmaf(__half2float(out_t[(size_t)i*FD + c]), w, acc);
    }
    sh[tid]=acc; __syncthreads();
    if(tid < 64){
        float v = (sh[tid]+sh[64+tid]+sh[128+tid]+sh[192+tid]) * inv;
        atomicAdd(&g_gout[b*FD+tid], v);
    }
}

// ---------------- gt = tanh(gout @ Wg + bg) ----------------
__global__ void gt_k(const float* __restrict__ Wg, const float* __restrict__ bg,
                     float* __restrict__ gt)
{
    __shared__ float sg[64];
    int b = blockIdx.x, f = threadIdx.x;
    sg[f] = g_gout[b*FD+f]; __syncthreads();
    float acc = 0.f;
#pragma unroll 8
    for(int c=0;c<64;c++) acc = fmaf(sg[c], Wg[c*64+f], acc);
    gt[b*FD+f] = tanhf(acc + bg[f]);
}

__global__ void scatt_k(const float* __restrict__ a, const float* __restrict__ abias)
{
    int b = blockIdx.x, lane = threadIdx.x;
    float l0=0.f,l1=0.f,l2=0.f;
    for(int f=lane; f<64; f+=32){
        float g0 = g_gt[0*NBD*FD + b*FD + f];
        float g1 = g_gt[1*NBD*FD + b*FD + f];
        float g2 = g_gt[2*NBD*FD + b*FD + f];
        l0 = fmaf(g0, a[f*3+0], l0);
        l1 = fmaf(g1, a[f*3+1], l1);
        l2 = fmaf(g2, a[f*3+2], l2);
    }
#pragma unroll
    for(int o=16;o;o>>=1){
        l0 += __shfl_xor_sync(0xffffffffu,l0,o);
        l1 += __shfl_xor_sync(0xffffffffu,l1,o);
        l2 += __shfl_xor_sync(0xffffffffu,l2,o);
    }
    if(lane==0){
        l0 += abias[0]; l1 += abias[1]; l2 += abias[2];
        float m = fmaxf(l0, fmaxf(l1,l2));
        float e0 = expf(l0-m), e1 = expf(l1-m), e2 = expf(l2-m);
        float inv = 1.f/(e0+e1+e2);
        g_scatt[b*3+0]=e0*inv; g_scatt[b*3+1]=e1*inv; g_scatt[b*3+2]=e2*inv;
    }
}

// ---------------- xn = x + gather(mixed fp16 out), fused lin1 stats --------
__global__ void xnmix_k(const float* __restrict__ x,
                        const __half* __restrict__ o0, const __half* __restrict__ o1,
                        const __half* __restrict__ o2, const int* __restrict__ batch,
                        float* __restrict__ xn, int N)
{
    __shared__ float ssm[FD], ssq[FD];
    int tid = threadIdx.x;
    if(tid < FD){ ssm[tid]=0.f; ssq[tid]=0.f; }
    __syncthreads();
    int n = (blockIdx.x*256 + tid) >> 3;
    int h = tid & 7;
    float a[8];
    if(n < N){
        const float4* px = (const float4*)(x + (size_t)n*FD);
        float4 X0 = px[2*h], X1 = px[2*h+1];
        a[0]=X0.x; a[1]=X0.y; a[2]=X0.z; a[3]=X0.w;
        a[4]=X1.x; a[5]=X1.y; a[6]=X1.z; a[7]=X1.w;
        int s = g_noffsets[n], t = g_noffsets[n+1];
        for(int k=s;k<t;k++){
            int e = g_nidx[k];
            int b = batch[e];
            float w0 = g_scatt[b*3], w1 = g_scatt[b*3+1], w2 = g_scatt[b*3+2];
            uint4 u0 = ((const uint4*)(o0 + (size_t)e*FD))[h];
            uint4 u1 = ((const uint4*)(o1 + (size_t)e*FD))[h];
            uint4 u2 = ((const uint4*)(o2 + (size_t)e*FD))[h];
            const uint32_t* p0 = &u0.x;
            const uint32_t* p1 = &u1.x;
            const uint32_t* p2 = &u2.x;
#pragma unroll
            for(int j=0;j<4;j++){
                float2 f0 = __half22float2(*(__half2*)&p0[j]);
                float2 f1 = __half22float2(*(__half2*)&p1[j]);
                float2 f2 = __half22float2(*(__half2*)&p2[j]);
                a[2*j  ] += f0.x*w0 + f1.x*w1 + f2.x*w2;
                a[2*j+1] += f0.y*w0 + f1.y*w1 + f2.y*w2;
            }
        }
        float4 W0, W1;
        W0.x=a[0]; W0.y=a[1]; W0.z=a[2]; W0.w=a[3];
        W1.x=a[4]; W1.y=a[5]; W1.z=a[6]; W1.w=a[7];
        float4* po = (float4*)(xn + (size_t)n*FD);
        po[2*h] = W0; po[2*h+1] = W1;
        int c0 = h*8;
#pragma unroll
        for(int j=0;j<8;j++){
            atomicAdd(&ssm[c0+j], a[j]);
            atomicAdd(&ssq[c0+j], a[j]*a[j]);
        }
    }
    __syncthreads();
    if(tid < FD){
        atomicAdd(&g_ssum5[tid], ssm[tid]);
        atomicAdd(&g_ssq5[tid],  ssq[tid]);
    }
}

// ---------------- host ----------------
extern "C" void kernel_launch(void* const* d_in, const int* in_sizes, int n_in,
                              void* d_out, int out_size)
{
    bool setupOrder = (in_sizes[2] > 100000);
    int IX, IEA, IEI, ILG, IBATCH, IWU, IWV, IWE, IGW, IAS, IAD, IGB, IA, IAB, IWG, IBG;
    int IB1G, IB1B, IW1, Ib1, IBNG, IBNB, IPR, IW, Ib, IB5G, IB5B, IPR5, IW5, Ib5;
    if(setupOrder){
        IX=0; IEA=1; IEI=2; ILG=3; IBATCH=4; IWU=5; IWV=6; IWE=7; IGW=8; IAS=9; IAD=10; IGB=11;
        IA=12; IAB=13; IWG=14; IBG=15; IB1G=16; IB1B=17; IW1=18; Ib1=19; IBNG=20; IBNB=21;
        IPR=22; IW=23; Ib=24; IB5G=25; IB5B=26; IPR5=27; IW5=28; Ib5=29;
    } else {
        IX=0; IEA=1; IWU=2; IWV=3; IWE=4; IGW=5; IAS=6; IAD=7; IGB=8; IA=9; IAB=10; IWG=11; IBG=12;
        IB1G=13; IB1B=14; IW1=15; Ib1=16; IBNG=17; IBNB=18; IPR=19; IW=20; Ib=21;
        IB5G=22; IB5B=23; IPR5=24; IW5=25; Ib5=26; IEI=27; ILG=28; IBATCH=29;
    }
    const float* x     = (const float*)d_in[IX];
    const float* eattr = (const float*)d_in[IEA];
    const int*   ei    = (const int*)d_in[IEI];
    const int*   lg    = (const int*)d_in[ILG];
    const int*   batch = (const int*)d_in[IBATCH];
    const float* W_u = (const float*)d_in[IWU];
    const float* W_v = (const float*)d_in[IWV];
    const float* W_e = (const float*)d_in[IWE];
    const float* gatW = (const float*)d_in[IGW];
    const float* asrc = (const float*)d_in[IAS];
    const float* adst = (const float*)d_in[IAD];
    const float* gbias = (const float*)d_in[IGB];
    const float* a_att = (const float*)d_in[IA];
    const float* a_bias = (const float*)d_in[IAB];
    const float* W_gout = (const float*)d_in[IWG];
    const float* b_gout = (const float*)d_in[IBG];
    const float* bn1g = (const float*)d_in[IB1G];
    const float* bn1b = (const float*)d_in[IB1B];
    const float* W1 = (const float*)d_in[IW1];
    const float* b1 = (const float*)d_in[Ib1];
    const float* bng = (const float*)d_in[IBNG];
    const float* bnb = (const float*)d_in[IBNB];
    const float* pr  = (const float*)d_in[IPR];
    const float* Wm  = (const float*)d_in[IW];
    const float* bm  = (const float*)d_in[Ib];
    const float* bn5g = (const float*)d_in[IB5G];
    const float* bn5b = (const float*)d_in[IB5B];
    const float* pr5 = (const float*)d_in[IPR5];
    const float* W5 = (const float*)d_in[IW5];
    const float* b5 = (const float*)d_in[Ib5];

    const int N  = in_sizes[IX] / FD;
    const int E  = in_sizes[IEA] / 16;
    const int LE = in_sizes[ILG] / 2;
    const int* ei0 = ei;       const int* ei1 = ei + E;
    const int* lg0 = lg;       const int* lg1 = lg + LE;

    void *p;
    float *xuv_p, *ea_p, *xn_p, *bufA, *bufB, *bufC, *gt_p, *xw_p;
    float *ssum5_p, *ssq5_p;
    __half *outh_p, *w1t, *wmt, *w5t;
    int *counts_p, *offsets_p, *cursor_p, *ncounts_p, *noffsets_p, *ncursor_p, *nidx_p, *idx_p;
    cudaGetSymbolAddress(&p, g_xuv);    xuv_p=(float*)p;
    cudaGetSymbolAddress(&p, g_ea);     ea_p=(float*)p;
    cudaGetSymbolAddress(&p, g_outh);   outh_p=(__half*)p;
    cudaGetSymbolAddress(&p, g_xn);     xn_p=(float*)p;
    cudaGetSymbolAddress(&p, g_bufA);   bufA=(float*)p;
    cudaGetSymbolAddress(&p, g_bufB);   bufB=(float*)p;
    cudaGetSymbolAddress(&p, g_bufC);   bufC=(float*)p;
    cudaGetSymbolAddress(&p, g_gt);     gt_p=(float*)p;
    cudaGetSymbolAddress(&p, g_xw);     xw_p=(float*)p;
    cudaGetSymbolAddress(&p, g_ssum5);  ssum5_p=(float*)p;
    cudaGetSymbolAddress(&p, g_ssq5);   ssq5_p=(float*)p;
    cudaGetSymbolAddress(&p, g_counts); counts_p=(int*)p;
    cudaGetSymbolAddress(&p, g_offsets);offsets_p=(int*)p;
    cudaGetSymbolAddress(&p, g_cursor); cursor_p=(int*)p;
    cudaGetSymbolAddress(&p, g_ncounts); ncounts_p=(int*)p;
    cudaGetSymbolAddress(&p, g_noffsets);noffsets_p=(int*)p;
    cudaGetSymbolAddress(&p, g_ncursor); ncursor_p=(int*)p;
    cudaGetSymbolAddress(&p, g_nidx);    nidx_p=(int*)p;
    cudaGetSymbolAddress(&p, g_idx);     idx_p=(int*)p;
    cudaGetSymbolAddress(&p, g_W1t);    w1t=(__half*)p;
    cudaGetSymbolAddress(&p, g_Wmt);    wmt=(__half*)p;
    cudaGetSymbolAddress(&p, g_W5t);    w5t=(__half*)p;

    static cudaStream_t s1 = nullptr;
    static cudaEvent_t ev0=nullptr, evCSR=nullptr, evNCSR=nullptr,
                       evM[NITD]={nullptr,nullptr,nullptr}, evScatt=nullptr, evCvt=nullptr;
    if(!s1){
        cudaStreamCreateWithFlags(&s1, cudaStreamNonBlocking);
        cudaEventCreateWithFlags(&ev0,    cudaEventDisableTiming);
        cudaEventCreateWithFlags(&evCSR,  cudaEventDisableTiming);
        cudaEventCreateWithFlags(&evNCSR, cudaEventDisableTiming);
        for(int t=0;t<NITD;t++) cudaEventCreateWithFlags(&evM[t], cudaEventDisableTiming);
        cudaEventCreateWithFlags(&evScatt,cudaEventDisableTiming);
        cudaEventCreateWithFlags(&evCvt,  cudaEventDisableTiming);
    }
    cudaStream_t s0 = 0;

    // ---- fork ----
    cudaEventRecord(ev0, s0);
    cudaStreamWaitEvent(s1, ev0, 0);

    // ===== s1: stats zero, weight conversion (fp16 transposed), CSRs =====
    zero_stats5_k<<<cdiv(5*SFD,256),256,0,s1>>>();
    cvtWh_k<<<cdiv(SFD*FD,256),256,0,s1>>>(W1, w1t, FD, SFD, SFD);           // Wt1 [384][64]
    for(int m=0;m<3;m++)
        cvtWh_k<<<cdiv(SFD*SFD,256),256,0,s1>>>(Wm + (size_t)m*SFD*SFD,
                                                wmt + (size_t)m*SFD*SFD, SFD, SFD, SFD);
    cvtWh_k<<<cdiv(128*SFD,256),256,0,s1>>>(W5, w5t, SFD, FD, 128);          // Wt5 [128][384]
    cudaEventRecord(evCvt, s1);
    cudaMemsetAsync(counts_p, 0, (size_t)E*sizeof(int), s1);
    hist_k<<<cdiv(LE,256),256,0,s1>>>(lg1, counts_p, LE);
    int nblkE = cdiv(E,1024);
    scan1_k<<<nblkE,1024,0,s1>>>(counts_p, offsets_p, E);
    scan2_k<<<1,512,0,s1>>>(nblkE);
    scan3_k<<<nblkE,1024,0,s1>>>(offsets_p, E, LE);
    cudaMemcpyAsync(cursor_p, offsets_p, (size_t)E*sizeof(int), cudaMemcpyDeviceToDevice, s1);
    fill_k<<<cdiv(LE,256),256,0,s1>>>(lg1, lg0, cursor_p, idx_p, LE);
    segstart_k<<<1,NBD+1,0,s1>>>(batch, E);
    cudaEventRecord(evCSR, s1);
    cudaMemsetAsync(ncounts_p, 0, (size_t)N*sizeof(int), s1);
    hist_k<<<cdiv(E,256),256,0,s1>>>(ei1, ncounts_p, E);
    int nblkN = cdiv(N,1024);
    scan1_k<<<nblkN,1024,0,s1>>>(ncounts_p, noffsets_p, N);
    scan2_k<<<1,512,0,s1>>>(nblkN);
    scan3_k<<<nblkN,1024,0,s1>>>(noffsets_p, N, E);
    cudaMemcpyAsync(ncursor_p, noffsets_p, (size_t)N*sizeof(int), cudaMemcpyDeviceToDevice, s1);
    fill_k<<<cdiv(E,256),256,0,s1>>>(ei1, nullptr, ncursor_p, nidx_p, E);
    cudaEventRecord(evNCSR, s1);

    // ===== s0: xuv -> ea =====
    gemm_xuv_k<<<dim3(cdiv(N,128),2),256,0,s0>>>(x, W_u, W_v, xuv_p, N);
    ea_kernel<<<cdiv(E,32),256,0,s0>>>(xuv_p, eattr, W_e, ei0, ei1, ea_p, E);

    // ===== iterations =====
    cudaStreamWaitEvent(s0, evCSR, 0);
    const size_t OSTRIDE = (size_t)MAXE*FD;
    for(int t=0;t<NITD;t++){
        __half* outt = outh_p + (size_t)t*OSTRIDE;
        float* xwt  = xw_p + (size_t)t*MAXE;
        if(t==0)
            msgpass_k<0><<<cdiv(E,32),256,0,s0>>>(ea_p, outt, ea_p, gatW, xwt, E);
        else
            msgpass_k<1><<<cdiv(E,32),256,0,s0>>>(outh_p + (size_t)(t-1)*OSTRIDE, outt,
                                                  ea_p, gatW, xwt, E);
        cudaEventRecord(evM[t], s0);
        cudaStreamWaitEvent(s1, evM[t], 0);
        xc_k<<<cdiv(E,256),256,0,s1>>>(asrc, adst, gbias, xwt, E);
        pool1_k<<<NBD,256,0,s1>>>();
        pool2_k<<<NBD*8,256,0,s1>>>(outt);
        gt_k<<<NBD,64,0,s1>>>(W_gout, b_gout, gt_p + (size_t)t*NBD*FD);
    }
    scatt_k<<<NBD,32,0,s1>>>(a_att, a_bias);
    cudaEventRecord(evScatt, s1);

    // ===== s0: xn (fused lin1 stats -> slot 0) -> LinearBlock =====
    cudaStreamWaitEvent(s0, evScatt, 0);
    cudaStreamWaitEvent(s0, evNCSR, 0);
    xnmix_k<<<cdiv(N,32),256,0,s0>>>(x, outh_p, outh_p+OSTRIDE, outh_p+2*OSTRIDE,
                                     batch, xn_p, N);

    cudaStreamWaitEvent(s0, evCvt, 0);
    gemm_tc<1,1><<<dim3(cdiv(N,128),SFD/128),256,0,s0>>>(xn_p, w1t, bufA, N, FD, SFD, FD,
        ssum5_p, ssq5_p, bn1g, bn1b, N, ssum5_p+SFD, ssq5_p+SFD, nullptr, b1, nullptr);
    gemm_tc<2,1><<<dim3(cdiv(N,128),SFD/128),256,0,s0>>>(bufA, wmt, bufB, N, SFD, SFD, SFD,
        ssum5_p+SFD, ssq5_p+SFD, bng, bnb, N, ssum5_p+2*SFD, ssq5_p+2*SFD, pr, bm, nullptr);
    gemm_tc<2,1><<<dim3(cdiv(N,128),SFD/128),256,0,s0>>>(bufB, wmt+(size_t)SFD*SFD, bufC, N, SFD, SFD, SFD,
        ssum5_p+2*SFD, ssq5_p+2*SFD, bng+SFD, bnb+SFD, N, ssum5_p+3*SFD, ssq5_p+3*SFD, pr+1, bm+SFD, bufA);
    gemm_tc<2,1><<<dim3(cdiv(N,128),SFD/128),256,0,s0>>>(bufC, wmt+(size_t)2*SFD*SFD, bufA, N, SFD, SFD, SFD,
        ssum5_p+3*SFD, ssq5_p+3*SFD, bng+2*SFD, bnb+2*SFD, N, ssum5_p+4*SFD, ssq5_p+4*SFD, pr+2, bm+2*SFD, bufC);
    gemm_tc<2,0><<<dim3(cdiv(N,128),1),256,0,s0>>>(bufA, w5t, (float*)d_out, N, SFD, FD, SFD,
        ssum5_p+4*SFD, ssq5_p+4*SFD, bn5g, bn5b, N, nullptr, nullptr, pr5, b5, nullptr);
}